// round 12
// baseline (speedup 1.0000x reference)
#include <cuda_runtime.h>
#include <cuda_bf16.h>
#include <math.h>
#include <stdint.h>

#define BB 2
#define TT 2048
#define DMM 512
#define HH 8
#define DD 64
#define UU 3
#define BH (BB*HH)

typedef unsigned long long u64;

// fp32 scratch
__device__ float g_Q[BH*TT*DD];    // [b,h,t,d]
__device__ float g_K[BH*TT*DD];
__device__ float g_V[BH*TT*DD];
__device__ int   g_top[BH*UU];
__device__ float g_part[BH*UU*8*68];
__device__ float g_kp[4*BH*TT*4];   // kl partials (zk*2+wn): m, Z, T, pad

// bf16 hi/lo packed (bf16x2 per uint), row-major
__device__ unsigned g_Xh[3*4096*256];   // [z][m][k/2]
__device__ unsigned g_Xl[3*4096*256];
__device__ unsigned g_Wh[3*512*256];    // [z][n][k/2]
__device__ unsigned g_Wl[3*512*256];
__device__ unsigned g_Qh[BH*TT*32];     // [bh][t][d/2]  (scaled by log2e/8)
__device__ unsigned g_Ql[BH*TT*32];
__device__ unsigned g_Kh[BH*TT*32];
__device__ unsigned g_Kl[BH*TT*32];

// ---------------------------------------------------------------------------
__device__ __forceinline__ uint32_t smem_u32(const void* p) {
    uint32_t a;
    asm("{ .reg .u64 t; cvta.to.shared.u64 t, %1; cvt.u32.u64 %0, t; }" : "=r"(a) : "l"(p));
    return a;
}
__device__ __forceinline__ void ldsm4(uint32_t addr, uint32_t& r0, uint32_t& r1,
                                      uint32_t& r2, uint32_t& r3) {
    asm volatile("ldmatrix.sync.aligned.m8n8.x4.shared.b16 {%0,%1,%2,%3}, [%4];"
                 : "=r"(r0), "=r"(r1), "=r"(r2), "=r"(r3) : "r"(addr));
}
__device__ __forceinline__ void mma_bf16(float& c0, float& c1, float& c2, float& c3,
                                         uint32_t a0, uint32_t a1, uint32_t a2, uint32_t a3,
                                         uint32_t b0, uint32_t b1) {
    asm("mma.sync.aligned.m16n8k16.row.col.f32.bf16.bf16.f32 "
        "{%0,%1,%2,%3}, {%4,%5,%6,%7}, {%8,%9}, {%0,%1,%2,%3};"
        : "+f"(c0), "+f"(c1), "+f"(c2), "+f"(c3)
        : "r"(a0), "r"(a1), "r"(a2), "r"(a3), "r"(b0), "r"(b1));
}
__device__ __forceinline__ float ex2f(float x) {
    float r;
    asm("ex2.approx.ftz.f32 %0, %1;" : "=f"(r) : "f"(x));
    return r;
}
#define CP_ASYNC16(dst, src) \
    asm volatile("cp.async.cg.shared.global [%0], [%1], 16;" :: "r"(dst), "l"(src))
#define CP_COMMIT() asm volatile("cp.async.commit_group;" ::: "memory")
#define CP_WAIT1()  asm volatile("cp.async.wait_group 1;" ::: "memory")
#define CP_WAIT0()  asm volatile("cp.async.wait_group 0;" ::: "memory")

// ---------------------------------------------------------------------------
// fp32 -> bf16 hi/lo split + fused conversion (X and W in one launch)
// ---------------------------------------------------------------------------
__device__ __forceinline__ void split8(const float* src, uint4& hi, uint4& lo) {
    float4 a = *(const float4*)src;
    float4 b = *(const float4*)(src + 4);
    float v[8] = {a.x, a.y, a.z, a.w, b.x, b.y, b.z, b.w};
    unsigned h16[8], l16[8];
#pragma unroll
    for (int i = 0; i < 8; i++) {
        __nv_bfloat16 h = __float2bfloat16_rn(v[i]);
        float r = v[i] - __bfloat162float(h);
        __nv_bfloat16 l = __float2bfloat16_rn(r);
        h16[i] = __bfloat16_as_ushort(h);
        l16[i] = __bfloat16_as_ushort(l);
    }
    hi = make_uint4(h16[0] | (h16[1] << 16), h16[2] | (h16[3] << 16),
                    h16[4] | (h16[5] << 16), h16[6] | (h16[7] << 16));
    lo = make_uint4(l16[0] | (l16[1] << 16), l16[2] | (l16[3] << 16),
                    l16[4] | (l16[5] << 16), l16[6] | (l16[7] << 16));
}

__global__ __launch_bounds__(256) void conv_kernel(
    const float* __restrict__ X0, const float* __restrict__ X1, const float* __restrict__ X2,
    const float* __restrict__ W0, const float* __restrict__ W1, const float* __restrict__ W2)
{
    const int z = blockIdx.y;
    if (blockIdx.x < 1024) {
        const float* X = (z == 0) ? X0 : (z == 1) ? X1 : X2;
        int idx = blockIdx.x * 256 + threadIdx.x;
        uint4 hi, lo;
        split8(X + (size_t)idx * 8, hi, lo);
        size_t di = (size_t)z * 4096 * 64 + idx;
        ((uint4*)g_Xh)[di] = hi;
        ((uint4*)g_Xl)[di] = lo;
    } else {
        const float* W = (z == 0) ? W0 : (z == 1) ? W1 : W2;
        int idx = (blockIdx.x - 1024) * 256 + threadIdx.x;
        uint4 hi, lo;
        split8(W + (size_t)idx * 8, hi, lo);
        size_t di = (size_t)z * 512 * 64 + idx;
        ((uint4*)g_Wh)[di] = hi;
        ((uint4*)g_Wl)[di] = lo;
    }
}

// ---------------------------------------------------------------------------
// Projection via mma.sync bf16 3-term split, cp.async double-buffered, k32
// stages with SW64 swizzle. grid (nt=4, mt=32, z=3), 256 thr. Tile 128x128.
// ---------------------------------------------------------------------------
__global__ __launch_bounds__(256, 2) void proj_mma_kernel(
    const float* __restrict__ B0, const float* __restrict__ B1, const float* __restrict__ B2,
    float* __restrict__ P0, float* __restrict__ P1, float* __restrict__ P2)
{
    extern __shared__ char dsm[];
    char* sbase = (char*)(((uintptr_t)dsm + 1023u) & ~(uintptr_t)1023u);
    const uint32_t sb = smem_u32(sbase);

    const int z = blockIdx.z;
    const float* Bv = (z == 0) ? B0 : (z == 1) ? B1 : B2;
    float*       P = (z == 0) ? P0 : (z == 1) ? P1 : P2;
    const int nt = blockIdx.x, mt = blockIdx.y;
    const int tid = threadIdx.x;
    const int wid = tid >> 5, lane = tid & 31;
    const int r = lane & 7, g = lane >> 3;
    const int wrow0 = wid * 16;
    const int m0 = mt * 128, n0 = nt * 128;

    float acc[16][4];
#pragma unroll
    for (int i = 0; i < 16; i++)
#pragma unroll
        for (int j = 0; j < 4; j++) acc[i][j] = 0.f;

    const int rowA = wrow0 + r + (g & 1) * 8;
    const int gbA = g >> 1;
    const int gbB = g & 1;
    const int rowBoff = r + ((g >> 1) & 1) * 8;

    const uint32_t rbA = (uint32_t)rowA * 64;
    const uint32_t maskA = (rbA >> 3) & 0x30;

    auto prefetch = [&](int kc) {
        uint32_t stg = sb + (kc & 1) * 32768;
#pragma unroll
        for (int j = 0; j < 2; j++) {
            int i = tid + j * 256;
            int row = i >> 2, c = i & 3;
            uint32_t boff = row * 64 + c * 16;
            uint32_t swb = boff ^ ((boff >> 3) & 0x30);
            size_t sx = (size_t)(z * 4096 + m0 + row) * 64 + kc * 4 + c;
            size_t swi = (size_t)(z * 512 + n0 + row) * 64 + kc * 4 + c;
            CP_ASYNC16(stg + swb,         (const uint4*)g_Xh + sx);
            CP_ASYNC16(stg + 8192 + swb,  (const uint4*)g_Xl + sx);
            CP_ASYNC16(stg + 16384 + swb, (const uint4*)g_Wh + swi);
            CP_ASYNC16(stg + 24576 + swb, (const uint4*)g_Wl + swi);
        }
    };

    prefetch(0); CP_COMMIT();

    for (int kc = 0; kc < 16; kc++) {
        if (kc < 15) { prefetch(kc + 1); CP_COMMIT(); CP_WAIT1(); }
        else CP_WAIT0();
        __syncthreads();
        const uint32_t stg = sb + (kc & 1) * 32768;
        const uint32_t abase = stg + rbA;

#pragma unroll
        for (int ks = 0; ks < 2; ks++) {
            uint32_t aoffs = ((uint32_t)((ks * 2 + gbA) * 16)) ^ maskA;
            uint32_t ah0, ah1, ah2, ah3, al0, al1, al2, al3;
            ldsm4(abase + aoffs, ah0, ah1, ah2, ah3);
            ldsm4(abase + 8192 + aoffs, al0, al1, al2, al3);
            uint32_t chunkB = (uint32_t)((ks * 2 + gbB) * 16);
#pragma unroll
            for (int np = 0; np < 8; np++) {
                uint32_t rbB = (uint32_t)(np * 16 + rowBoff) * 64;
                uint32_t boffs = chunkB ^ ((rbB >> 3) & 0x30);
                uint32_t bbase = stg + 16384 + rbB + boffs;
                uint32_t bh0, bh1, bh2, bh3, bl0, bl1, bl2, bl3;
                ldsm4(bbase, bh0, bh1, bh2, bh3);
                ldsm4(bbase + 8192, bl0, bl1, bl2, bl3);
                int f0 = np * 2, f1 = np * 2 + 1;
                mma_bf16(acc[f0][0], acc[f0][1], acc[f0][2], acc[f0][3],
                         ah0, ah1, ah2, ah3, bh0, bh1);
                mma_bf16(acc[f1][0], acc[f1][1], acc[f1][2], acc[f1][3],
                         ah0, ah1, ah2, ah3, bh2, bh3);
                mma_bf16(acc[f0][0], acc[f0][1], acc[f0][2], acc[f0][3],
                         ah0, ah1, ah2, ah3, bl0, bl1);
                mma_bf16(acc[f1][0], acc[f1][1], acc[f1][2], acc[f1][3],
                         ah0, ah1, ah2, ah3, bl2, bl3);
                mma_bf16(acc[f0][0], acc[f0][1], acc[f0][2], acc[f0][3],
                         al0, al1, al2, al3, bh0, bh1);
                mma_bf16(acc[f1][0], acc[f1][1], acc[f1][2], acc[f1][3],
                         al0, al1, al2, al3, bh2, bh3);
            }
        }
        __syncthreads();
    }

    const float QSCALE = 0.18033688011112042f;   // 0.125 * log2(e)
    const int mrow0 = m0 + wrow0 + (lane >> 2);
#pragma unroll
    for (int half = 0; half < 2; half++) {
        int m = mrow0 + half * 8;
        int b = m >> 11, t = m & 2047;
#pragma unroll
        for (int nf = 0; nf < 16; nf++) {
            int n = n0 + nf * 8 + 2 * (lane & 3);
            int h = n >> 6, d = n & 63;
            float2 bias = *(const float2*)(Bv + n);
            float v0 = acc[nf][half * 2] + bias.x;
            float v1 = acc[nf][half * 2 + 1] + bias.y;
            size_t po = (((size_t)(b * HH + h)) * TT + t) * DD + d;
            *(float2*)&P[po] = make_float2(v0, v1);
            if (z < 2) {
                float s0 = v0, s1 = v1;
                if (z == 0) { s0 *= QSCALE; s1 *= QSCALE; }
                __nv_bfloat16 h0 = __float2bfloat16_rn(s0);
                __nv_bfloat16 h1 = __float2bfloat16_rn(s1);
                float l0 = s0 - __bfloat162float(h0);
                float l1 = s1 - __bfloat162float(h1);
                unsigned hp = (unsigned)__bfloat16_as_ushort(h0) |
                              ((unsigned)__bfloat16_as_ushort(h1) << 16);
                unsigned lp = (unsigned)__bfloat16_as_ushort(__float2bfloat16_rn(l0)) |
                              ((unsigned)__bfloat16_as_ushort(__float2bfloat16_rn(l1)) << 16);
                size_t qo = (((size_t)(b * HH + h)) * TT + t) * 32 + (d >> 1);
                if (z == 0) { g_Qh[qo] = hp; g_Ql[qo] = lp; }
                else        { g_Kh[qo] = hp; g_Kl[qo] = lp; }
            }
        }
    }
}

// ---------------------------------------------------------------------------
// KL statistic: base-2 online softmax, split-K (zk=2), warp tiling 4m x 2n
// (warp tile 32q x 64k) to halve LDSM B traffic. Q fragments direct from gmem.
// grid (qt=16, bh=16, zk=2), 256 thr. smem: 2 K stages x 32KB.
// ---------------------------------------------------------------------------
__global__ __launch_bounds__(256) void kl_mma_kernel() {
    extern __shared__ char dsm[];
    char* sbase = (char*)(((uintptr_t)dsm + 1023u) & ~(uintptr_t)1023u);
    const uint32_t sb = smem_u32(sbase);

    const int tid = threadIdx.x;
    const int wid = tid >> 5, lane = tid & 31;
    const int wm = wid & 3, wn = wid >> 2;
    const int r = lane & 7, g = lane >> 3;
    const int bh = blockIdx.y;
    const int q0 = blockIdx.x * 128;
    const int zk = blockIdx.z;

    auto prefetchK = [&](int ktl) {
        uint32_t stg = sb + (ktl & 1) * 32768;
        int ktg = zk * 8 + ktl;
#pragma unroll
        for (int j = 0; j < 4; j++) {
            int i = tid + j * 256;
            int row = i >> 3, c = i & 7;
            uint32_t boff = row * 128 + c * 16;
            uint32_t swb = boff ^ ((boff >> 3) & 0x70);
            size_t sidx = (size_t)(bh * TT + ktg * 128 + row) * 8 + c;
            CP_ASYNC16(stg + swb,         (const uint4*)g_Kh + sidx);
            CP_ASYNC16(stg + 16384 + swb, (const uint4*)g_Kl + sidx);
        }
    };

    prefetchK(0); CP_COMMIT();

    // Q fragments for 32 rows (2 m-frags), 4 k-steps, direct from gmem
    uint32_t Ah[2][4][4], Al[2][4][4];
#pragma unroll
    for (int mf = 0; mf < 2; mf++) {
        const int row0 = q0 + wm * 32 + mf * 16 + (lane >> 2);
        const size_t qb0 = ((size_t)bh * TT + row0) * 32;
        const size_t qb1 = qb0 + 8 * 32;
#pragma unroll
        for (int ks = 0; ks < 4; ks++) {
            int cu = ks * 8 + (lane & 3);
            Ah[mf][ks][0] = g_Qh[qb0 + cu];
            Ah[mf][ks][1] = g_Qh[qb1 + cu];
            Ah[mf][ks][2] = g_Qh[qb0 + cu + 4];
            Ah[mf][ks][3] = g_Qh[qb1 + cu + 4];
            Al[mf][ks][0] = g_Ql[qb0 + cu];
            Al[mf][ks][1] = g_Ql[qb1 + cu];
            Al[mf][ks][2] = g_Ql[qb0 + cu + 4];
            Al[mf][ks][3] = g_Ql[qb1 + cu + 4];
        }
    }

    float mst[4], Zc[4], Tc[4];   // slot = mf*2 + h2
#pragma unroll
    for (int s = 0; s < 4; s++) { mst[s] = -1e30f; Zc[s] = 0.f; Tc[s] = 0.f; }

    const int gbB = g & 1;
    const int rowBoff = r + ((g >> 1) & 1) * 8;

    for (int ktl = 0; ktl < 8; ktl++) {
        if (ktl < 7) { prefetchK(ktl + 1); CP_COMMIT(); CP_WAIT1(); }
        else CP_WAIT0();
        __syncthreads();
        const uint32_t stg = sb + (ktl & 1) * 32768;

        float acc[2][8][4];
#pragma unroll
        for (int mf = 0; mf < 2; mf++)
#pragma unroll
            for (int i = 0; i < 8; i++)
#pragma unroll
                for (int j = 0; j < 4; j++) acc[mf][i][j] = 0.f;

#pragma unroll
        for (int ks = 0; ks < 4; ks++) {
            uint32_t boffs = ((uint32_t)((ks * 2 + gbB) * 16)) ^ (uint32_t)(r * 16);
#pragma unroll
            for (int np = 0; np < 4; np++) {
                uint32_t bbase = stg + (wn * 64 + np * 16 + rowBoff) * 128 + boffs;
                uint32_t bh0, bh1, bh2, bh3, bl0, bl1, bl2, bl3;
                ldsm4(bbase, bh0, bh1, bh2, bh3);
                ldsm4(bbase + 16384, bl0, bl1, bl2, bl3);
                int f0 = np * 2, f1 = np * 2 + 1;
#pragma unroll
                for (int mf = 0; mf < 2; mf++) {
                    mma_bf16(acc[mf][f0][0], acc[mf][f0][1], acc[mf][f0][2], acc[mf][f0][3],
                             Ah[mf][ks][0], Ah[mf][ks][1], Ah[mf][ks][2], Ah[mf][ks][3], bh0, bh1);
                    mma_bf16(acc[mf][f1][0], acc[mf][f1][1], acc[mf][f1][2], acc[mf][f1][3],
                             Ah[mf][ks][0], Ah[mf][ks][1], Ah[mf][ks][2], Ah[mf][ks][3], bh2, bh3);
                    mma_bf16(acc[mf][f0][0], acc[mf][f0][1], acc[mf][f0][2], acc[mf][f0][3],
                             Ah[mf][ks][0], Ah[mf][ks][1], Ah[mf][ks][2], Ah[mf][ks][3], bl0, bl1);
                    mma_bf16(acc[mf][f1][0], acc[mf][f1][1], acc[mf][f1][2], acc[mf][f1][3],
                             Ah[mf][ks][0], Ah[mf][ks][1], Ah[mf][ks][2], Ah[mf][ks][3], bl2, bl3);
                    mma_bf16(acc[mf][f0][0], acc[mf][f0][1], acc[mf][f0][2], acc[mf][f0][3],
                             Al[mf][ks][0], Al[mf][ks][1], Al[mf][ks][2], Al[mf][ks][3], bh0, bh1);
                    mma_bf16(acc[mf][f1][0], acc[mf][f1][1], acc[mf][f1][2], acc[mf][f1][3],
                             Al[mf][ks][0], Al[mf][ks][1], Al[mf][ks][2], Al[mf][ks][3], bh2, bh3);
                }
            }
        }

        // base-2 online softmax/KL update (log2-domain scores)
#pragma unroll
        for (int mf = 0; mf < 2; mf++)
#pragma unroll
            for (int h2 = 0; h2 < 2; h2++) {
                int s = mf * 2 + h2;
                float tmax = -1e30f;
#pragma unroll
                for (int nf = 0; nf < 8; nf++)
                    tmax = fmaxf(tmax, fmaxf(acc[mf][nf][h2 * 2], acc[mf][nf][h2 * 2 + 1]));
                float nm = fmaxf(mst[s], tmax);
                float f = ex2f(mst[s] - nm);
                float zs = 0.f, ts = 0.f;
#pragma unroll
                for (int nf = 0; nf < 8; nf++) {
                    float u0 = acc[mf][nf][h2 * 2];
                    float u1 = acc[mf][nf][h2 * 2 + 1];
                    float e0 = ex2f(u0 - nm);
                    float e1 = ex2f(u1 - nm);
                    zs += e0 + e1;
                    ts = fmaf(e0, u0, ts);
                    ts = fmaf(e1, u1, ts);
                }
                Zc[s] = Zc[s] * f + zs;
                Tc[s] = Tc[s] * f + ts;
                mst[s] = nm;
            }
        __syncthreads();
    }

    // merge across 4 lanes per row, store partial (slot zk*2+wn)
    const int slot = zk * 2 + wn;
#pragma unroll
    for (int mf = 0; mf < 2; mf++)
#pragma unroll
        for (int h2 = 0; h2 < 2; h2++) {
            int s = mf * 2 + h2;
#pragma unroll
            for (int off = 1; off < 4; off <<= 1) {
                float mo = __shfl_xor_sync(0xffffffffu, mst[s], off, 4);
                float zo = __shfl_xor_sync(0xffffffffu, Zc[s],  off, 4);
                float to = __shfl_xor_sync(0xffffffffu, Tc[s],  off, 4);
                float nm = fmaxf(mst[s], mo);
                float f1 = ex2f(mst[s] - nm), f2 = ex2f(mo - nm);
                Zc[s] = Zc[s] * f1 + zo * f2;
                Tc[s] = Tc[s] * f1 + to * f2;
                mst[s] = nm;
            }
            if ((lane & 3) == 0) {
                int q = q0 + wm * 32 + mf * 16 + (lane >> 2) + h2 * 8;
                size_t o = ((size_t)slot * BH * TT + (size_t)bh * TT + q) * 4;
                *(float4*)&g_kp[o] = make_float4(mst[s], Zc[s], Tc[s], 0.f);
            }
        }
}

// ---------------------------------------------------------------------------
// Top-3 per (b,h): merge 4 KL partials into smem, then select (jax ties)
// ---------------------------------------------------------------------------
__global__ void top3_kernel() {
    const int bh = blockIdx.x;
    __shared__ float skl[TT];
    __shared__ float sv[256];
    __shared__ int   si[256];
    __shared__ int   chosen[UU];

    for (int q = threadIdx.x; q < TT; q += 256) {
        float m = -1e30f, Z = 0.f, T = 0.f;
#pragma unroll
        for (int p = 0; p < 4; p++) {
            float4 pp = *(float4*)&g_kp[((size_t)p * BH * TT + (size_t)bh * TT + q) * 4];
            float nm = fmaxf(m, pp.x);
            float f1 = ex2f(m - nm), f2 = ex2f(pp.x - nm);
            Z = Z * f1 + pp.y * f2;
            T = T * f1 + pp.z * f2;
            m = nm;
        }
        skl[q] = 0.6931471805599453f * (T / Z - m - log2f(Z));
    }
    __syncthreads();

    for (int p = 0; p < UU; p++) {
        float bv = -1e38f; int bi = TT;
        for (int q = threadIdx.x; q < TT; q += 256) {
            bool skip = false;
            for (int c = 0; c < p; c++) if (chosen[c] == q) skip = true;
            if (skip) continue;
            float v = skl[q];
            if (v > bv || (v == bv && q < bi)) { bv = v; bi = q; }
        }
        sv[threadIdx.x] = bv; si[threadIdx.x] = bi;
        __syncthreads();
        for (int s = 128; s > 0; s >>= 1) {
            if (threadIdx.x < s) {
                float ov = sv[threadIdx.x + s]; int oi = si[threadIdx.x + s];
                if (ov > sv[threadIdx.x] ||
                    (ov == sv[threadIdx.x] && oi < si[threadIdx.x])) {
                    sv[threadIdx.x] = ov; si[threadIdx.x] = oi;
                }
            }
            __syncthreads();
        }
        if (threadIdx.x == 0) { chosen[p] = si[0]; g_top[bh * UU + p] = si[0]; }
        __syncthreads();
    }
}

// ---------------------------------------------------------------------------
// Reduced attention, split-K: grid (48 slots, 8 parts), 256 keys per part.
// ---------------------------------------------------------------------------
__global__ __launch_bounds__(256) void redattn_part_kernel() {
    const int slot = blockIdx.x;
    const int part = blockIdx.y;
    const int bh = slot / UU;
    const int t = g_top[slot];
    __shared__ float qrow[64];
    __shared__ float sarr[256];
    __shared__ float red[256];
    const int tid = threadIdx.x;

    if (tid < 64) qrow[tid] = g_Q[((size_t)bh * TT + t) * DD + tid];
    __syncthreads();

    const int k = part * 256 + tid;
    {
        const float* kr = g_K + ((size_t)bh * TT + k) * DD;
        float s = 0.f;
#pragma unroll
        for (int d = 0; d < 64; d++) s = fmaf(qrow[d], kr[d], s);
        s *= 0.125f;
        if (!(s == s)) s = -10000.0f;
        s = fminf(fmaxf(s, -10000.0f), 10000.0f);
        sarr[tid] = s;
        red[tid] = s;
    }
    __syncthreads();
    for (int s = 128; s > 0; s >>= 1) {
        if (tid < s) red[tid] = fmaxf(red[tid], red[tid + s]);
        __syncthreads();
    }
    const float mx = red[0];
    __syncthreads();

    float e = expf(sarr[tid] - mx);
    sarr[tid] = e;
    red[tid] = e;
    __syncthreads();
    for (int s = 128; s > 0; s >>= 1) {
        if (tid < s) red[tid] += red[tid + s];
        __syncthreads();
    }
    const float Zp = red[0];
    __syncthreads();

    const int d = tid % 64, gi = tid / 64;
    float acc = 0.f;
    for (int kk = gi; kk < 256; kk += 4)
        acc = fmaf(sarr[kk], g_V[((size_t)bh * TT + part * 256 + kk) * DD + d], acc);
    red[tid] = acc; __syncthreads();

    float* pp = g_part + (size_t)(slot * 8 + part) * 68;
    if (tid == 0) { pp[0] = mx; pp[1] = Zp; }
    if (tid < 64)
        pp[2 + tid] = red[tid] + red[tid + 64] + red[tid + 128] + red[tid + 192];
}

// ---------------------------------------------------------------------------
// Output: init to bias; scatter fuses the redattn combine + Wo projection
// ---------------------------------------------------------------------------
__global__ void init_out_kernel(float* __restrict__ out, const float* __restrict__ bo) {
    int idx = blockIdx.x * 256 + threadIdx.x;
    if (idx < BB * TT * DMM) out[idx] = bo[idx % DMM];
}

__global__ void scatter_kernel(const float* __restrict__ Wo, float* __restrict__ out) {
    const int slot = blockIdx.x;
    const int bh = slot / UU;
    const int b = bh / HH, h = bh % HH;
    const int t = g_top[slot];
    __shared__ float orow[64];

    if (threadIdx.x < 64) {
        const int d = threadIdx.x;
        float mstar = -1e30f;
#pragma unroll
        for (int p = 0; p < 8; p++)
            mstar = fmaxf(mstar, g_part[(size_t)(slot * 8 + p) * 68]);
        float Z = 0.f, acc = 0.f;
#pragma unroll
        for (int p = 0; p < 8; p++) {
            const float* pp = g_part + (size_t)(slot * 8 + p) * 68;
            float f = expf(pp[0] - mstar);
            Z += pp[1] * f;
            acc += pp[2 + d] * f;
        }
        orow[d] = acc / Z;
    }
    __syncthreads();

    for (int n = threadIdx.x; n < DMM; n += 256) {
        const float* wr = Wo + (size_t)n * DMM + h * DD;
        float acc = 0.f;
#pragma unroll
        for (int d = 0; d < 64; d++) acc = fmaf(orow[d], wr[d], acc);
        atomicAdd(&out[((size_t)b * TT + t) * DMM + n], acc);
    }
}

// ---------------------------------------------------------------------------
extern "C" void kernel_launch(void* const* d_in, const int* in_sizes, int n_in,
                              void* d_out, int out_size) {
    const float* query = (const float*)d_in[0];
    const float* key   = (const float*)d_in[1];
    const float* value = (const float*)d_in[2];
    const float* Wq = (const float*)d_in[3];
    const float* bq = (const float*)d_in[4];
    const float* Wk = (const float*)d_in[5];
    const float* bk = (const float*)d_in[6];
    const float* Wv = (const float*)d_in[7];
    const float* bv = (const float*)d_in[8];
    const float* Wo = (const float*)d_in[9];
    const float* bo = (const float*)d_in[10];
    float* out = (float*)d_out;

    float *Qp, *Kp, *Vp;
    cudaGetSymbolAddress((void**)&Qp, g_Q);
    cudaGetSymbolAddress((void**)&Kp, g_K);
    cudaGetSymbolAddress((void**)&Vp, g_V);

    const int proj_smem = 65536 + 1024;
    const int kl_smem   = 65536 + 1024;
    cudaFuncSetAttribute(proj_mma_kernel, cudaFuncAttributeMaxDynamicSharedMemorySize, proj_smem);
    cudaFuncSetAttribute(kl_mma_kernel,   cudaFuncAttributeMaxDynamicSharedMemorySize, kl_smem);

    conv_kernel<<<dim3(1152, 3), 256>>>(query, key, value, Wq, Wk, Wv);

    proj_mma_kernel<<<dim3(4, 32, 3), 256, proj_smem>>>(bq, bk, bv, Qp, Kp, Vp);

    kl_mma_kernel<<<dim3(16, 16, 2), 256, kl_smem>>>();

    top3_kernel<<<BH, 256>>>();
    redattn_part_kernel<<<dim3(BH * UU, 8), 256>>>();

    init_out_kernel<<<(BB * TT * DMM + 255) / 256, 256>>>(out, bo);
    scatter_kernel<<<BH * UU, 256>>>(Wo, out);
}

// round 13
// speedup vs baseline: 1.0665x; 1.0665x over previous
#include <cuda_runtime.h>
#include <cuda_bf16.h>
#include <math.h>
#include <stdint.h>

#define BB 2
#define TT 2048
#define DMM 512
#define HH 8
#define DD 64
#define UU 3
#define BH (BB*HH)

typedef unsigned long long u64;

// fp32 scratch
__device__ float g_Q[BH*TT*DD];    // [b,h,t,d]
__device__ float g_K[BH*TT*DD];
__device__ float g_V[BH*TT*DD];
__device__ int   g_top[BH*UU];
__device__ float g_part[BH*UU*8*68];
__device__ float g_kp[2*BH*TT*4];   // kl split-K partials: m, Z, T, pad

// bf16 hi/lo packed (bf16x2 per uint), row-major
__device__ unsigned g_Xh[3*4096*256];   // [z][m][k/2]
__device__ unsigned g_Xl[3*4096*256];
__device__ unsigned g_Wh[3*512*256];    // [z][n][k/2]
__device__ unsigned g_Wl[3*512*256];
__device__ unsigned g_Qh[BH*TT*32];     // [bh][t][d/2]  (scaled by log2e/8)
__device__ unsigned g_Ql[BH*TT*32];
__device__ unsigned g_Kh[BH*TT*32];
__device__ unsigned g_Kl[BH*TT*32];

// ---------------------------------------------------------------------------
__device__ __forceinline__ uint32_t smem_u32(const void* p) {
    uint32_t a;
    asm("{ .reg .u64 t; cvta.to.shared.u64 t, %1; cvt.u32.u64 %0, t; }" : "=r"(a) : "l"(p));
    return a;
}
__device__ __forceinline__ void ldsm4(uint32_t addr, uint32_t& r0, uint32_t& r1,
                                      uint32_t& r2, uint32_t& r3) {
    asm volatile("ldmatrix.sync.aligned.m8n8.x4.shared.b16 {%0,%1,%2,%3}, [%4];"
                 : "=r"(r0), "=r"(r1), "=r"(r2), "=r"(r3) : "r"(addr));
}
__device__ __forceinline__ void mma_bf16(float& c0, float& c1, float& c2, float& c3,
                                         uint32_t a0, uint32_t a1, uint32_t a2, uint32_t a3,
                                         uint32_t b0, uint32_t b1) {
    asm("mma.sync.aligned.m16n8k16.row.col.f32.bf16.bf16.f32 "
        "{%0,%1,%2,%3}, {%4,%5,%6,%7}, {%8,%9}, {%0,%1,%2,%3};"
        : "+f"(c0), "+f"(c1), "+f"(c2), "+f"(c3)
        : "r"(a0), "r"(a1), "r"(a2), "r"(a3), "r"(b0), "r"(b1));
}
__device__ __forceinline__ float ex2f(float x) {
    float r;
    asm("ex2.approx.ftz.f32 %0, %1;" : "=f"(r) : "f"(x));
    return r;
}
#define CP_ASYNC16(dst, src) \
    asm volatile("cp.async.cg.shared.global [%0], [%1], 16;" :: "r"(dst), "l"(src))
#define CP_COMMIT() asm volatile("cp.async.commit_group;" ::: "memory")
#define CP_WAIT1()  asm volatile("cp.async.wait_group 1;" ::: "memory")
#define CP_WAIT0()  asm volatile("cp.async.wait_group 0;" ::: "memory")

// ---------------------------------------------------------------------------
// fp32 -> bf16 hi/lo split + fused conversion (X and W in one launch)
// ---------------------------------------------------------------------------
__device__ __forceinline__ void split8(const float* src, uint4& hi, uint4& lo) {
    float4 a = *(const float4*)src;
    float4 b = *(const float4*)(src + 4);
    float v[8] = {a.x, a.y, a.z, a.w, b.x, b.y, b.z, b.w};
    unsigned h16[8], l16[8];
#pragma unroll
    for (int i = 0; i < 8; i++) {
        __nv_bfloat16 h = __float2bfloat16_rn(v[i]);
        float r = v[i] - __bfloat162float(h);
        __nv_bfloat16 l = __float2bfloat16_rn(r);
        h16[i] = __bfloat16_as_ushort(h);
        l16[i] = __bfloat16_as_ushort(l);
    }
    hi = make_uint4(h16[0] | (h16[1] << 16), h16[2] | (h16[3] << 16),
                    h16[4] | (h16[5] << 16), h16[6] | (h16[7] << 16));
    lo = make_uint4(l16[0] | (l16[1] << 16), l16[2] | (l16[3] << 16),
                    l16[4] | (l16[5] << 16), l16[6] | (l16[7] << 16));
}

__global__ __launch_bounds__(256) void conv_kernel(
    const float* __restrict__ X0, const float* __restrict__ X1, const float* __restrict__ X2,
    const float* __restrict__ W0, const float* __restrict__ W1, const float* __restrict__ W2)
{
    const int z = blockIdx.y;
    if (blockIdx.x < 1024) {
        const float* X = (z == 0) ? X0 : (z == 1) ? X1 : X2;
        int idx = blockIdx.x * 256 + threadIdx.x;
        uint4 hi, lo;
        split8(X + (size_t)idx * 8, hi, lo);
        size_t di = (size_t)z * 4096 * 64 + idx;
        ((uint4*)g_Xh)[di] = hi;
        ((uint4*)g_Xl)[di] = lo;
    } else {
        const float* W = (z == 0) ? W0 : (z == 1) ? W1 : W2;
        int idx = (blockIdx.x - 1024) * 256 + threadIdx.x;
        uint4 hi, lo;
        split8(W + (size_t)idx * 8, hi, lo);
        size_t di = (size_t)z * 512 * 64 + idx;
        ((uint4*)g_Wh)[di] = hi;
        ((uint4*)g_Wl)[di] = lo;
    }
}

// ---------------------------------------------------------------------------
// Projection via mma.sync bf16 3-term split, cp.async double-buffered, k32
// stages with SW64 swizzle. grid (nt=4, mt=32, z=3), 256 thr. Tile 128x128.
// ---------------------------------------------------------------------------
__global__ __launch_bounds__(256, 2) void proj_mma_kernel(
    const float* __restrict__ B0, const float* __restrict__ B1, const float* __restrict__ B2,
    float* __restrict__ P0, float* __restrict__ P1, float* __restrict__ P2)
{
    extern __shared__ char dsm[];
    char* sbase = (char*)(((uintptr_t)dsm + 1023u) & ~(uintptr_t)1023u);
    const uint32_t sb = smem_u32(sbase);

    const int z = blockIdx.z;
    const float* Bv = (z == 0) ? B0 : (z == 1) ? B1 : B2;
    float*       P = (z == 0) ? P0 : (z == 1) ? P1 : P2;
    const int nt = blockIdx.x, mt = blockIdx.y;
    const int tid = threadIdx.x;
    const int wid = tid >> 5, lane = tid & 31;
    const int r = lane & 7, g = lane >> 3;
    const int wrow0 = wid * 16;
    const int m0 = mt * 128, n0 = nt * 128;

    float acc[16][4];
#pragma unroll
    for (int i = 0; i < 16; i++)
#pragma unroll
        for (int j = 0; j < 4; j++) acc[i][j] = 0.f;

    const int rowA = wrow0 + r + (g & 1) * 8;
    const int gbA = g >> 1;
    const int gbB = g & 1;
    const int rowBoff = r + ((g >> 1) & 1) * 8;

    const uint32_t rbA = (uint32_t)rowA * 64;
    const uint32_t maskA = (rbA >> 3) & 0x30;

    auto prefetch = [&](int kc) {
        uint32_t stg = sb + (kc & 1) * 32768;
#pragma unroll
        for (int j = 0; j < 2; j++) {
            int i = tid + j * 256;
            int row = i >> 2, c = i & 3;
            uint32_t boff = row * 64 + c * 16;
            uint32_t swb = boff ^ ((boff >> 3) & 0x30);
            size_t sx = (size_t)(z * 4096 + m0 + row) * 64 + kc * 4 + c;
            size_t swi = (size_t)(z * 512 + n0 + row) * 64 + kc * 4 + c;
            CP_ASYNC16(stg + swb,         (const uint4*)g_Xh + sx);
            CP_ASYNC16(stg + 8192 + swb,  (const uint4*)g_Xl + sx);
            CP_ASYNC16(stg + 16384 + swb, (const uint4*)g_Wh + swi);
            CP_ASYNC16(stg + 24576 + swb, (const uint4*)g_Wl + swi);
        }
    };

    prefetch(0); CP_COMMIT();

    for (int kc = 0; kc < 16; kc++) {
        if (kc < 15) { prefetch(kc + 1); CP_COMMIT(); CP_WAIT1(); }
        else CP_WAIT0();
        __syncthreads();
        const uint32_t stg = sb + (kc & 1) * 32768;
        const uint32_t abase = stg + rbA;

#pragma unroll
        for (int ks = 0; ks < 2; ks++) {
            uint32_t aoffs = ((uint32_t)((ks * 2 + gbA) * 16)) ^ maskA;
            uint32_t ah0, ah1, ah2, ah3, al0, al1, al2, al3;
            ldsm4(abase + aoffs, ah0, ah1, ah2, ah3);
            ldsm4(abase + 8192 + aoffs, al0, al1, al2, al3);
            uint32_t chunkB = (uint32_t)((ks * 2 + gbB) * 16);
#pragma unroll
            for (int np = 0; np < 8; np++) {
                uint32_t rbB = (uint32_t)(np * 16 + rowBoff) * 64;
                uint32_t boffs = chunkB ^ ((rbB >> 3) & 0x30);
                uint32_t bbase = stg + 16384 + rbB + boffs;
                uint32_t bh0, bh1, bh2, bh3, bl0, bl1, bl2, bl3;
                ldsm4(bbase, bh0, bh1, bh2, bh3);
                ldsm4(bbase + 8192, bl0, bl1, bl2, bl3);
                int f0 = np * 2, f1 = np * 2 + 1;
                mma_bf16(acc[f0][0], acc[f0][1], acc[f0][2], acc[f0][3],
                         ah0, ah1, ah2, ah3, bh0, bh1);
                mma_bf16(acc[f1][0], acc[f1][1], acc[f1][2], acc[f1][3],
                         ah0, ah1, ah2, ah3, bh2, bh3);
                mma_bf16(acc[f0][0], acc[f0][1], acc[f0][2], acc[f0][3],
                         ah0, ah1, ah2, ah3, bl0, bl1);
                mma_bf16(acc[f1][0], acc[f1][1], acc[f1][2], acc[f1][3],
                         ah0, ah1, ah2, ah3, bl2, bl3);
                mma_bf16(acc[f0][0], acc[f0][1], acc[f0][2], acc[f0][3],
                         al0, al1, al2, al3, bh0, bh1);
                mma_bf16(acc[f1][0], acc[f1][1], acc[f1][2], acc[f1][3],
                         al0, al1, al2, al3, bh2, bh3);
            }
        }
        __syncthreads();
    }

    const float QSCALE = 0.18033688011112042f;   // 0.125 * log2(e)
    const int mrow0 = m0 + wrow0 + (lane >> 2);
#pragma unroll
    for (int half = 0; half < 2; half++) {
        int m = mrow0 + half * 8;
        int b = m >> 11, t = m & 2047;
#pragma unroll
        for (int nf = 0; nf < 16; nf++) {
            int n = n0 + nf * 8 + 2 * (lane & 3);
            int h = n >> 6, d = n & 63;
            float2 bias = *(const float2*)(Bv + n);
            float v0 = acc[nf][half * 2] + bias.x;
            float v1 = acc[nf][half * 2 + 1] + bias.y;
            size_t po = (((size_t)(b * HH + h)) * TT + t) * DD + d;
            *(float2*)&P[po] = make_float2(v0, v1);
            if (z < 2) {
                float s0 = v0, s1 = v1;
                if (z == 0) { s0 *= QSCALE; s1 *= QSCALE; }
                __nv_bfloat16 h0 = __float2bfloat16_rn(s0);
                __nv_bfloat16 h1 = __float2bfloat16_rn(s1);
                float l0 = s0 - __bfloat162float(h0);
                float l1 = s1 - __bfloat162float(h1);
                unsigned hp = (unsigned)__bfloat16_as_ushort(h0) |
                              ((unsigned)__bfloat16_as_ushort(h1) << 16);
                unsigned lp = (unsigned)__bfloat16_as_ushort(__float2bfloat16_rn(l0)) |
                              ((unsigned)__bfloat16_as_ushort(__float2bfloat16_rn(l1)) << 16);
                size_t qo = (((size_t)(b * HH + h)) * TT + t) * 32 + (d >> 1);
                if (z == 0) { g_Qh[qo] = hp; g_Ql[qo] = lp; }
                else        { g_Kh[qo] = hp; g_Kl[qo] = lp; }
            }
        }
    }
}

// ---------------------------------------------------------------------------
// KL statistic (R11-proven shape): base-2 online softmax, split-K (zk=2),
// 8 warps x full-128-N, Q fragments direct from gmem.
// grid (qt=16, bh=16, zk=2), 256 thr. smem: 2 K stages x 32KB.
// ---------------------------------------------------------------------------
__global__ __launch_bounds__(256, 2) void kl_mma_kernel() {
    extern __shared__ char dsm[];
    char* sbase = (char*)(((uintptr_t)dsm + 1023u) & ~(uintptr_t)1023u);
    const uint32_t sb = smem_u32(sbase);

    const int tid = threadIdx.x;
    const int wid = tid >> 5, lane = tid & 31;
    const int r = lane & 7, g = lane >> 3;
    const int wrow0 = wid * 16;
    const int bh = blockIdx.y;
    const int q0 = blockIdx.x * 128;
    const int zk = blockIdx.z;

    auto prefetchK = [&](int ktl) {
        uint32_t stg = sb + (ktl & 1) * 32768;
        int ktg = zk * 8 + ktl;
#pragma unroll
        for (int j = 0; j < 4; j++) {
            int i = tid + j * 256;
            int row = i >> 3, c = i & 7;
            uint32_t boff = row * 128 + c * 16;
            uint32_t swb = boff ^ ((boff >> 3) & 0x70);
            size_t sidx = (size_t)(bh * TT + ktg * 128 + row) * 8 + c;
            CP_ASYNC16(stg + swb,         (const uint4*)g_Kh + sidx);
            CP_ASYNC16(stg + 16384 + swb, (const uint4*)g_Kl + sidx);
        }
    };

    prefetchK(0); CP_COMMIT();

    uint32_t Ah[4][4], Al[4][4];
    {
        const int row0 = q0 + wrow0 + (lane >> 2);
        const size_t qb0 = ((size_t)bh * TT + row0) * 32;
        const size_t qb1 = qb0 + 8 * 32;
#pragma unroll
        for (int ks = 0; ks < 4; ks++) {
            int cu = ks * 8 + (lane & 3);
            Ah[ks][0] = g_Qh[qb0 + cu];
            Ah[ks][1] = g_Qh[qb1 + cu];
            Ah[ks][2] = g_Qh[qb0 + cu + 4];
            Ah[ks][3] = g_Qh[qb1 + cu + 4];
            Al[ks][0] = g_Ql[qb0 + cu];
            Al[ks][1] = g_Ql[qb1 + cu];
            Al[ks][2] = g_Ql[qb0 + cu + 4];
            Al[ks][3] = g_Ql[qb1 + cu + 4];
        }
    }

    float mst[2] = {-1e30f, -1e30f}, Zc[2] = {0.f, 0.f}, Tc[2] = {0.f, 0.f};
    const int gbB = g & 1;
    const int rowBoff = r + ((g >> 1) & 1) * 8;

    for (int ktl = 0; ktl < 8; ktl++) {
        if (ktl < 7) { prefetchK(ktl + 1); CP_COMMIT(); CP_WAIT1(); }
        else CP_WAIT0();
        __syncthreads();
        const uint32_t stg = sb + (ktl & 1) * 32768;

        float acc[16][4];
#pragma unroll
        for (int i = 0; i < 16; i++)
#pragma unroll
            for (int j = 0; j < 4; j++) acc[i][j] = 0.f;

#pragma unroll
        for (int ks = 0; ks < 4; ks++) {
            uint32_t boffs = ((uint32_t)((ks * 2 + gbB) * 16)) ^ (uint32_t)(r * 16);
#pragma unroll
            for (int np = 0; np < 8; np++) {
                uint32_t bbase = stg + (np * 16 + rowBoff) * 128 + boffs;
                uint32_t bh0, bh1, bh2, bh3, bl0, bl1, bl2, bl3;
                ldsm4(bbase, bh0, bh1, bh2, bh3);
                ldsm4(bbase + 16384, bl0, bl1, bl2, bl3);
                int f0 = np * 2, f1 = np * 2 + 1;
                mma_bf16(acc[f0][0], acc[f0][1], acc[f0][2], acc[f0][3],
                         Ah[ks][0], Ah[ks][1], Ah[ks][2], Ah[ks][3], bh0, bh1);
                mma_bf16(acc[f1][0], acc[f1][1], acc[f1][2], acc[f1][3],
                         Ah[ks][0], Ah[ks][1], Ah[ks][2], Ah[ks][3], bh2, bh3);
                mma_bf16(acc[f0][0], acc[f0][1], acc[f0][2], acc[f0][3],
                         Ah[ks][0], Ah[ks][1], Ah[ks][2], Ah[ks][3], bl0, bl1);
                mma_bf16(acc[f1][0], acc[f1][1], acc[f1][2], acc[f1][3],
                         Ah[ks][0], Ah[ks][1], Ah[ks][2], Ah[ks][3], bl2, bl3);
                mma_bf16(acc[f0][0], acc[f0][1], acc[f0][2], acc[f0][3],
                         Al[ks][0], Al[ks][1], Al[ks][2], Al[ks][3], bh0, bh1);
                mma_bf16(acc[f1][0], acc[f1][1], acc[f1][2], acc[f1][3],
                         Al[ks][0], Al[ks][1], Al[ks][2], Al[ks][3], bh2, bh3);
            }
        }

#pragma unroll
        for (int h2 = 0; h2 < 2; h2++) {
            float tmax = -1e30f;
#pragma unroll
            for (int nf = 0; nf < 16; nf++)
                tmax = fmaxf(tmax, fmaxf(acc[nf][h2 * 2], acc[nf][h2 * 2 + 1]));
            float nm = fmaxf(mst[h2], tmax);
            float f = ex2f(mst[h2] - nm);
            float zs = 0.f, ts = 0.f;
#pragma unroll
            for (int nf = 0; nf < 16; nf++) {
                float u0 = acc[nf][h2 * 2];
                float u1 = acc[nf][h2 * 2 + 1];
                float e0 = ex2f(u0 - nm);
                float e1 = ex2f(u1 - nm);
                zs += e0 + e1;
                ts = fmaf(e0, u0, ts);
                ts = fmaf(e1, u1, ts);
            }
            Zc[h2] = Zc[h2] * f + zs;
            Tc[h2] = Tc[h2] * f + ts;
            mst[h2] = nm;
        }
        __syncthreads();
    }

#pragma unroll
    for (int h2 = 0; h2 < 2; h2++) {
#pragma unroll
        for (int off = 1; off < 4; off <<= 1) {
            float mo = __shfl_xor_sync(0xffffffffu, mst[h2], off, 4);
            float zo = __shfl_xor_sync(0xffffffffu, Zc[h2],  off, 4);
            float to = __shfl_xor_sync(0xffffffffu, Tc[h2],  off, 4);
            float nm = fmaxf(mst[h2], mo);
            float f1 = ex2f(mst[h2] - nm), f2 = ex2f(mo - nm);
            Zc[h2] = Zc[h2] * f1 + zo * f2;
            Tc[h2] = Tc[h2] * f1 + to * f2;
            mst[h2] = nm;
        }
        if ((lane & 3) == 0) {
            int q = q0 + wrow0 + (lane >> 2) + h2 * 8;
            size_t o = ((size_t)zk * BH * TT + (size_t)bh * TT + q) * 4;
            *(float4*)&g_kp[o] = make_float4(mst[h2], Zc[h2], Tc[h2], 0.f);
        }
    }
}

// ---------------------------------------------------------------------------
// Top-3 per (b,h): single-pass. Fuses the 2-partial KL merge; each thread
// keeps a sorted local top-3 (value desc, index asc on ties = jax), then a
// log-tree merge across the block.
// ---------------------------------------------------------------------------
__device__ __forceinline__ bool cand_better(float av, int ai, float bv, int bi) {
    return av > bv || (av == bv && ai < bi);
}

__global__ void top3_kernel() {
    const int bh = blockIdx.x;
    __shared__ float sv[256 * 3];
    __shared__ int   si[256 * 3];
    const int tid = threadIdx.x;

    float tv[3] = {-1e38f, -1e38f, -1e38f};
    int   ti[3] = {TT, TT, TT};

    for (int q = tid; q < TT; q += 256) {
        float4 p0 = *(float4*)&g_kp[((size_t)bh * TT + q) * 4];
        float4 p1 = *(float4*)&g_kp[((size_t)BH * TT + (size_t)bh * TT + q) * 4];
        float nm = fmaxf(p0.x, p1.x);
        float f0 = ex2f(p0.x - nm), f1 = ex2f(p1.x - nm);
        float Z = p0.y * f0 + p1.y * f1;
        float T = p0.z * f0 + p1.z * f1;
        float v = 0.6931471805599453f * (T / Z - nm - log2f(Z));

        if (cand_better(v, q, tv[0], ti[0])) {
            tv[2] = tv[1]; ti[2] = ti[1];
            tv[1] = tv[0]; ti[1] = ti[0];
            tv[0] = v; ti[0] = q;
        } else if (cand_better(v, q, tv[1], ti[1])) {
            tv[2] = tv[1]; ti[2] = ti[1];
            tv[1] = v; ti[1] = q;
        } else if (cand_better(v, q, tv[2], ti[2])) {
            tv[2] = v; ti[2] = q;
        }
    }

    sv[tid*3+0] = tv[0]; si[tid*3+0] = ti[0];
    sv[tid*3+1] = tv[1]; si[tid*3+1] = ti[1];
    sv[tid*3+2] = tv[2]; si[tid*3+2] = ti[2];
    __syncthreads();

    for (int s = 128; s > 0; s >>= 1) {
        if (tid < s) {
            // merge triples tid and tid+s (both sorted) -> top-3 into tid
            float av[3], bvv[3]; int ai[3], bii[3];
#pragma unroll
            for (int j = 0; j < 3; j++) {
                av[j] = sv[tid*3+j];        ai[j] = si[tid*3+j];
                bvv[j] = sv[(tid+s)*3+j];   bii[j] = si[(tid+s)*3+j];
            }
            float ov[3]; int oi[3];
            int pa = 0, pb = 0;
#pragma unroll
            for (int j = 0; j < 3; j++) {
                if (cand_better(av[pa], ai[pa], bvv[pb], bii[pb])) {
                    ov[j] = av[pa]; oi[j] = ai[pa]; pa++;
                } else {
                    ov[j] = bvv[pb]; oi[j] = bii[pb]; pb++;
                }
            }
#pragma unroll
            for (int j = 0; j < 3; j++) { sv[tid*3+j] = ov[j]; si[tid*3+j] = oi[j]; }
        }
        __syncthreads();
    }

    if (tid < UU) g_top[bh * UU + tid] = si[tid];
}

// ---------------------------------------------------------------------------
// Reduced attention, split-K: grid (48 slots, 8 parts), 256 keys per part.
// ---------------------------------------------------------------------------
__global__ __launch_bounds__(256) void redattn_part_kernel() {
    const int slot = blockIdx.x;
    const int part = blockIdx.y;
    const int bh = slot / UU;
    const int t = g_top[slot];
    __shared__ float qrow[64];
    __shared__ float sarr[256];
    __shared__ float red[256];
    const int tid = threadIdx.x;

    if (tid < 64) qrow[tid] = g_Q[((size_t)bh * TT + t) * DD + tid];
    __syncthreads();

    const int k = part * 256 + tid;
    {
        const float* kr = g_K + ((size_t)bh * TT + k) * DD;
        float s = 0.f;
#pragma unroll
        for (int d = 0; d < 64; d++) s = fmaf(qrow[d], kr[d], s);
        s *= 0.125f;
        if (!(s == s)) s = -10000.0f;
        s = fminf(fmaxf(s, -10000.0f), 10000.0f);
        sarr[tid] = s;
        red[tid] = s;
    }
    __syncthreads();
    for (int s = 128; s > 0; s >>= 1) {
        if (tid < s) red[tid] = fmaxf(red[tid], red[tid + s]);
        __syncthreads();
    }
    const float mx = red[0];
    __syncthreads();

    float e = expf(sarr[tid] - mx);
    sarr[tid] = e;
    red[tid] = e;
    __syncthreads();
    for (int s = 128; s > 0; s >>= 1) {
        if (tid < s) red[tid] += red[tid + s];
        __syncthreads();
    }
    const float Zp = red[0];
    __syncthreads();

    const int d = tid % 64, gi = tid / 64;
    float acc = 0.f;
    for (int kk = gi; kk < 256; kk += 4)
        acc = fmaf(sarr[kk], g_V[((size_t)bh * TT + part * 256 + kk) * DD + d], acc);
    red[tid] = acc; __syncthreads();

    float* pp = g_part + (size_t)(slot * 8 + part) * 68;
    if (tid == 0) { pp[0] = mx; pp[1] = Zp; }
    if (tid < 64)
        pp[2 + tid] = red[tid] + red[tid + 64] + red[tid + 128] + red[tid + 192];
}

// ---------------------------------------------------------------------------
// Output: init to bias; scatter fuses the redattn combine + Wo projection
// ---------------------------------------------------------------------------
__global__ void init_out_kernel(float* __restrict__ out, const float* __restrict__ bo) {
    int idx = blockIdx.x * 256 + threadIdx.x;
    if (idx < BB * TT * DMM) out[idx] = bo[idx % DMM];
}

__global__ void scatter_kernel(const float* __restrict__ Wo, float* __restrict__ out) {
    const int slot = blockIdx.x;
    const int bh = slot / UU;
    const int b = bh / HH, h = bh % HH;
    const int t = g_top[slot];
    __shared__ float orow[64];

    if (threadIdx.x < 64) {
        const int d = threadIdx.x;
        float mstar = -1e30f;
#pragma unroll
        for (int p = 0; p < 8; p++)
            mstar = fmaxf(mstar, g_part[(size_t)(slot * 8 + p) * 68]);
        float Z = 0.f, acc = 0.f;
#pragma unroll
        for (int p = 0; p < 8; p++) {
            const float* pp = g_part + (size_t)(slot * 8 + p) * 68;
            float f = expf(pp[0] - mstar);
            Z += pp[1] * f;
            acc += pp[2 + d] * f;
        }
        orow[d] = acc / Z;
    }
    __syncthreads();

    for (int n = threadIdx.x; n < DMM; n += 256) {
        const float* wr = Wo + (size_t)n * DMM + h * DD;
        float acc = 0.f;
#pragma unroll
        for (int d = 0; d < 64; d++) acc = fmaf(orow[d], wr[d], acc);
        atomicAdd(&out[((size_t)b * TT + t) * DMM + n], acc);
    }
}

// ---------------------------------------------------------------------------
extern "C" void kernel_launch(void* const* d_in, const int* in_sizes, int n_in,
                              void* d_out, int out_size) {
    const float* query = (const float*)d_in[0];
    const float* key   = (const float*)d_in[1];
    const float* value = (const float*)d_in[2];
    const float* Wq = (const float*)d_in[3];
    const float* bq = (const float*)d_in[4];
    const float* Wk = (const float*)d_in[5];
    const float* bk = (const float*)d_in[6];
    const float* Wv = (const float*)d_in[7];
    const float* bv = (const float*)d_in[8];
    const float* Wo = (const float*)d_in[9];
    const float* bo = (const float*)d_in[10];
    float* out = (float*)d_out;

    float *Qp, *Kp, *Vp;
    cudaGetSymbolAddress((void**)&Qp, g_Q);
    cudaGetSymbolAddress((void**)&Kp, g_K);
    cudaGetSymbolAddress((void**)&Vp, g_V);

    const int proj_smem = 65536 + 1024;
    const int kl_smem   = 65536 + 1024;
    cudaFuncSetAttribute(proj_mma_kernel, cudaFuncAttributeMaxDynamicSharedMemorySize, proj_smem);
    cudaFuncSetAttribute(kl_mma_kernel,   cudaFuncAttributeMaxDynamicSharedMemorySize, kl_smem);

    conv_kernel<<<dim3(1152, 3), 256>>>(query, key, value, Wq, Wk, Wv);

    proj_mma_kernel<<<dim3(4, 32, 3), 256, proj_smem>>>(bq, bk, bv, Qp, Kp, Vp);

    kl_mma_kernel<<<dim3(16, 16, 2), 256, kl_smem>>>();

    top3_kernel<<<BH, 256>>>();
    redattn_part_kernel<<<dim3(BH * UU, 8), 256>>>();

    init_out_kernel<<<(BB * TT * DMM + 255) / 256, 256>>>(out, bo);
    scatter_kernel<<<BH * UU, 256>>>(Wo, out);
}

// round 14
// speedup vs baseline: 1.0879x; 1.0201x over previous
#include <cuda_runtime.h>
#include <cuda_bf16.h>
#include <math.h>
#include <stdint.h>

#define BB 2
#define TT 2048
#define DMM 512
#define HH 8
#define DD 64
#define UU 3
#define BH (BB*HH)

typedef unsigned long long u64;

// fp32 scratch
__device__ float g_Q[BH*TT*DD];    // [b,h,t,d]
__device__ float g_K[BH*TT*DD];
__device__ float g_V[BH*TT*DD];
__device__ float g_part[BH*UU*8*68];
__device__ float g_kp[2*BH*TT*4];   // kl split-K partials: m, Z, T, pad
__device__ float g_t3v[BH*8*3];     // per-(bh,seg) top-3 values (sorted)
__device__ int   g_t3i[BH*8*3];     // per-(bh,seg) top-3 indices

// bf16 hi/lo packed (bf16x2 per uint), row-major
__device__ unsigned g_Xh[3*4096*256];   // [z][m][k/2]
__device__ unsigned g_Xl[3*4096*256];
__device__ unsigned g_Wh[3*512*256];    // [z][n][k/2]
__device__ unsigned g_Wl[3*512*256];
__device__ unsigned g_Qh[BH*TT*32];     // [bh][t][d/2]  (scaled by log2e/8)
__device__ unsigned g_Ql[BH*TT*32];
__device__ unsigned g_Kh[BH*TT*32];
__device__ unsigned g_Kl[BH*TT*32];

// ---------------------------------------------------------------------------
__device__ __forceinline__ uint32_t smem_u32(const void* p) {
    uint32_t a;
    asm("{ .reg .u64 t; cvta.to.shared.u64 t, %1; cvt.u32.u64 %0, t; }" : "=r"(a) : "l"(p));
    return a;
}
__device__ __forceinline__ void ldsm4(uint32_t addr, uint32_t& r0, uint32_t& r1,
                                      uint32_t& r2, uint32_t& r3) {
    asm volatile("ldmatrix.sync.aligned.m8n8.x4.shared.b16 {%0,%1,%2,%3}, [%4];"
                 : "=r"(r0), "=r"(r1), "=r"(r2), "=r"(r3) : "r"(addr));
}
__device__ __forceinline__ void mma_bf16(float& c0, float& c1, float& c2, float& c3,
                                         uint32_t a0, uint32_t a1, uint32_t a2, uint32_t a3,
                                         uint32_t b0, uint32_t b1) {
    asm("mma.sync.aligned.m16n8k16.row.col.f32.bf16.bf16.f32 "
        "{%0,%1,%2,%3}, {%4,%5,%6,%7}, {%8,%9}, {%0,%1,%2,%3};"
        : "+f"(c0), "+f"(c1), "+f"(c2), "+f"(c3)
        : "r"(a0), "r"(a1), "r"(a2), "r"(a3), "r"(b0), "r"(b1));
}
__device__ __forceinline__ float ex2f(float x) {
    float r;
    asm("ex2.approx.ftz.f32 %0, %1;" : "=f"(r) : "f"(x));
    return r;
}
#define CP_ASYNC16(dst, src) \
    asm volatile("cp.async.cg.shared.global [%0], [%1], 16;" :: "r"(dst), "l"(src))
#define CP_COMMIT() asm volatile("cp.async.commit_group;" ::: "memory")
#define CP_WAIT1()  asm volatile("cp.async.wait_group 1;" ::: "memory")
#define CP_WAIT0()  asm volatile("cp.async.wait_group 0;" ::: "memory")

// ---------------------------------------------------------------------------
// fp32 -> bf16 hi/lo split + fused conversion (X and W in one launch)
// ---------------------------------------------------------------------------
__device__ __forceinline__ void split8(const float* src, uint4& hi, uint4& lo) {
    float4 a = *(const float4*)src;
    float4 b = *(const float4*)(src + 4);
    float v[8] = {a.x, a.y, a.z, a.w, b.x, b.y, b.z, b.w};
    unsigned h16[8], l16[8];
#pragma unroll
    for (int i = 0; i < 8; i++) {
        __nv_bfloat16 h = __float2bfloat16_rn(v[i]);
        float r = v[i] - __bfloat162float(h);
        __nv_bfloat16 l = __float2bfloat16_rn(r);
        h16[i] = __bfloat16_as_ushort(h);
        l16[i] = __bfloat16_as_ushort(l);
    }
    hi = make_uint4(h16[0] | (h16[1] << 16), h16[2] | (h16[3] << 16),
                    h16[4] | (h16[5] << 16), h16[6] | (h16[7] << 16));
    lo = make_uint4(l16[0] | (l16[1] << 16), l16[2] | (l16[3] << 16),
                    l16[4] | (l16[5] << 16), l16[6] | (l16[7] << 16));
}

__global__ __launch_bounds__(256) void conv_kernel(
    const float* __restrict__ X0, const float* __restrict__ X1, const float* __restrict__ X2,
    const float* __restrict__ W0, const float* __restrict__ W1, const float* __restrict__ W2)
{
    const int z = blockIdx.y;
    if (blockIdx.x < 1024) {
        const float* X = (z == 0) ? X0 : (z == 1) ? X1 : X2;
        int idx = blockIdx.x * 256 + threadIdx.x;
        uint4 hi, lo;
        split8(X + (size_t)idx * 8, hi, lo);
        size_t di = (size_t)z * 4096 * 64 + idx;
        ((uint4*)g_Xh)[di] = hi;
        ((uint4*)g_Xl)[di] = lo;
    } else {
        const float* W = (z == 0) ? W0 : (z == 1) ? W1 : W2;
        int idx = (blockIdx.x - 1024) * 256 + threadIdx.x;
        uint4 hi, lo;
        split8(W + (size_t)idx * 8, hi, lo);
        size_t di = (size_t)z * 512 * 64 + idx;
        ((uint4*)g_Wh)[di] = hi;
        ((uint4*)g_Wl)[di] = lo;
    }
}

// ---------------------------------------------------------------------------
// Projection via mma.sync bf16 3-term split, cp.async double-buffered, k32
// stages with SW64 swizzle. grid (nt=4, mt=32, z=3), 256 thr. Tile 128x128.
// ---------------------------------------------------------------------------
__global__ __launch_bounds__(256, 2) void proj_mma_kernel(
    const float* __restrict__ B0, const float* __restrict__ B1, const float* __restrict__ B2,
    float* __restrict__ P0, float* __restrict__ P1, float* __restrict__ P2)
{
    extern __shared__ char dsm[];
    char* sbase = (char*)(((uintptr_t)dsm + 1023u) & ~(uintptr_t)1023u);
    const uint32_t sb = smem_u32(sbase);

    const int z = blockIdx.z;
    const float* Bv = (z == 0) ? B0 : (z == 1) ? B1 : B2;
    float*       P = (z == 0) ? P0 : (z == 1) ? P1 : P2;
    const int nt = blockIdx.x, mt = blockIdx.y;
    const int tid = threadIdx.x;
    const int wid = tid >> 5, lane = tid & 31;
    const int r = lane & 7, g = lane >> 3;
    const int wrow0 = wid * 16;
    const int m0 = mt * 128, n0 = nt * 128;

    float acc[16][4];
#pragma unroll
    for (int i = 0; i < 16; i++)
#pragma unroll
        for (int j = 0; j < 4; j++) acc[i][j] = 0.f;

    const int rowA = wrow0 + r + (g & 1) * 8;
    const int gbA = g >> 1;
    const int gbB = g & 1;
    const int rowBoff = r + ((g >> 1) & 1) * 8;

    const uint32_t rbA = (uint32_t)rowA * 64;
    const uint32_t maskA = (rbA >> 3) & 0x30;

    auto prefetch = [&](int kc) {
        uint32_t stg = sb + (kc & 1) * 32768;
#pragma unroll
        for (int j = 0; j < 2; j++) {
            int i = tid + j * 256;
            int row = i >> 2, c = i & 3;
            uint32_t boff = row * 64 + c * 16;
            uint32_t swb = boff ^ ((boff >> 3) & 0x30);
            size_t sx = (size_t)(z * 4096 + m0 + row) * 64 + kc * 4 + c;
            size_t swi = (size_t)(z * 512 + n0 + row) * 64 + kc * 4 + c;
            CP_ASYNC16(stg + swb,         (const uint4*)g_Xh + sx);
            CP_ASYNC16(stg + 8192 + swb,  (const uint4*)g_Xl + sx);
            CP_ASYNC16(stg + 16384 + swb, (const uint4*)g_Wh + swi);
            CP_ASYNC16(stg + 24576 + swb, (const uint4*)g_Wl + swi);
        }
    };

    prefetch(0); CP_COMMIT();

    for (int kc = 0; kc < 16; kc++) {
        if (kc < 15) { prefetch(kc + 1); CP_COMMIT(); CP_WAIT1(); }
        else CP_WAIT0();
        __syncthreads();
        const uint32_t stg = sb + (kc & 1) * 32768;
        const uint32_t abase = stg + rbA;

#pragma unroll
        for (int ks = 0; ks < 2; ks++) {
            uint32_t aoffs = ((uint32_t)((ks * 2 + gbA) * 16)) ^ maskA;
            uint32_t ah0, ah1, ah2, ah3, al0, al1, al2, al3;
            ldsm4(abase + aoffs, ah0, ah1, ah2, ah3);
            ldsm4(abase + 8192 + aoffs, al0, al1, al2, al3);
            uint32_t chunkB = (uint32_t)((ks * 2 + gbB) * 16);
#pragma unroll
            for (int np = 0; np < 8; np++) {
                uint32_t rbB = (uint32_t)(np * 16 + rowBoff) * 64;
                uint32_t boffs = chunkB ^ ((rbB >> 3) & 0x30);
                uint32_t bbase = stg + 16384 + rbB + boffs;
                uint32_t bh0, bh1, bh2, bh3, bl0, bl1, bl2, bl3;
                ldsm4(bbase, bh0, bh1, bh2, bh3);
                ldsm4(bbase + 8192, bl0, bl1, bl2, bl3);
                int f0 = np * 2, f1 = np * 2 + 1;
                mma_bf16(acc[f0][0], acc[f0][1], acc[f0][2], acc[f0][3],
                         ah0, ah1, ah2, ah3, bh0, bh1);
                mma_bf16(acc[f1][0], acc[f1][1], acc[f1][2], acc[f1][3],
                         ah0, ah1, ah2, ah3, bh2, bh3);
                mma_bf16(acc[f0][0], acc[f0][1], acc[f0][2], acc[f0][3],
                         ah0, ah1, ah2, ah3, bl0, bl1);
                mma_bf16(acc[f1][0], acc[f1][1], acc[f1][2], acc[f1][3],
                         ah0, ah1, ah2, ah3, bl2, bl3);
                mma_bf16(acc[f0][0], acc[f0][1], acc[f0][2], acc[f0][3],
                         al0, al1, al2, al3, bh0, bh1);
                mma_bf16(acc[f1][0], acc[f1][1], acc[f1][2], acc[f1][3],
                         al0, al1, al2, al3, bh2, bh3);
            }
        }
        __syncthreads();
    }

    const float QSCALE = 0.18033688011112042f;   // 0.125 * log2(e)
    const int mrow0 = m0 + wrow0 + (lane >> 2);
#pragma unroll
    for (int half = 0; half < 2; half++) {
        int m = mrow0 + half * 8;
        int b = m >> 11, t = m & 2047;
#pragma unroll
        for (int nf = 0; nf < 16; nf++) {
            int n = n0 + nf * 8 + 2 * (lane & 3);
            int h = n >> 6, d = n & 63;
            float2 bias = *(const float2*)(Bv + n);
            float v0 = acc[nf][half * 2] + bias.x;
            float v1 = acc[nf][half * 2 + 1] + bias.y;
            size_t po = (((size_t)(b * HH + h)) * TT + t) * DD + d;
            *(float2*)&P[po] = make_float2(v0, v1);
            if (z < 2) {
                float s0 = v0, s1 = v1;
                if (z == 0) { s0 *= QSCALE; s1 *= QSCALE; }
                __nv_bfloat16 h0 = __float2bfloat16_rn(s0);
                __nv_bfloat16 h1 = __float2bfloat16_rn(s1);
                float l0 = s0 - __bfloat162float(h0);
                float l1 = s1 - __bfloat162float(h1);
                unsigned hp = (unsigned)__bfloat16_as_ushort(h0) |
                              ((unsigned)__bfloat16_as_ushort(h1) << 16);
                unsigned lp = (unsigned)__bfloat16_as_ushort(__float2bfloat16_rn(l0)) |
                              ((unsigned)__bfloat16_as_ushort(__float2bfloat16_rn(l1)) << 16);
                size_t qo = (((size_t)(b * HH + h)) * TT + t) * 32 + (d >> 1);
                if (z == 0) { g_Qh[qo] = hp; g_Ql[qo] = lp; }
                else        { g_Kh[qo] = hp; g_Kl[qo] = lp; }
            }
        }
    }
}

// ---------------------------------------------------------------------------
// KL statistic (R11-proven shape): base-2 online softmax, split-K (zk=2),
// 8 warps x full-128-N, Q fragments direct from gmem.
// grid (qt=16, bh=16, zk=2), 256 thr. smem: 2 K stages x 32KB.
// ---------------------------------------------------------------------------
__global__ __launch_bounds__(256, 2) void kl_mma_kernel() {
    extern __shared__ char dsm[];
    char* sbase = (char*)(((uintptr_t)dsm + 1023u) & ~(uintptr_t)1023u);
    const uint32_t sb = smem_u32(sbase);

    const int tid = threadIdx.x;
    const int wid = tid >> 5, lane = tid & 31;
    const int r = lane & 7, g = lane >> 3;
    const int wrow0 = wid * 16;
    const int bh = blockIdx.y;
    const int q0 = blockIdx.x * 128;
    const int zk = blockIdx.z;

    auto prefetchK = [&](int ktl) {
        uint32_t stg = sb + (ktl & 1) * 32768;
        int ktg = zk * 8 + ktl;
#pragma unroll
        for (int j = 0; j < 4; j++) {
            int i = tid + j * 256;
            int row = i >> 3, c = i & 7;
            uint32_t boff = row * 128 + c * 16;
            uint32_t swb = boff ^ ((boff >> 3) & 0x70);
            size_t sidx = (size_t)(bh * TT + ktg * 128 + row) * 8 + c;
            CP_ASYNC16(stg + swb,         (const uint4*)g_Kh + sidx);
            CP_ASYNC16(stg + 16384 + swb, (const uint4*)g_Kl + sidx);
        }
    };

    prefetchK(0); CP_COMMIT();

    uint32_t Ah[4][4], Al[4][4];
    {
        const int row0 = q0 + wrow0 + (lane >> 2);
        const size_t qb0 = ((size_t)bh * TT + row0) * 32;
        const size_t qb1 = qb0 + 8 * 32;
#pragma unroll
        for (int ks = 0; ks < 4; ks++) {
            int cu = ks * 8 + (lane & 3);
            Ah[ks][0] = g_Qh[qb0 + cu];
            Ah[ks][1] = g_Qh[qb1 + cu];
            Ah[ks][2] = g_Qh[qb0 + cu + 4];
            Ah[ks][3] = g_Qh[qb1 + cu + 4];
            Al[ks][0] = g_Ql[qb0 + cu];
            Al[ks][1] = g_Ql[qb1 + cu];
            Al[ks][2] = g_Ql[qb0 + cu + 4];
            Al[ks][3] = g_Ql[qb1 + cu + 4];
        }
    }

    float mst[2] = {-1e30f, -1e30f}, Zc[2] = {0.f, 0.f}, Tc[2] = {0.f, 0.f};
    const int gbB = g & 1;
    const int rowBoff = r + ((g >> 1) & 1) * 8;

    for (int ktl = 0; ktl < 8; ktl++) {
        if (ktl < 7) { prefetchK(ktl + 1); CP_COMMIT(); CP_WAIT1(); }
        else CP_WAIT0();
        __syncthreads();
        const uint32_t stg = sb + (ktl & 1) * 32768;

        float acc[16][4];
#pragma unroll
        for (int i = 0; i < 16; i++)
#pragma unroll
            for (int j = 0; j < 4; j++) acc[i][j] = 0.f;

#pragma unroll
        for (int ks = 0; ks < 4; ks++) {
            uint32_t boffs = ((uint32_t)((ks * 2 + gbB) * 16)) ^ (uint32_t)(r * 16);
#pragma unroll
            for (int np = 0; np < 8; np++) {
                uint32_t bbase = stg + (np * 16 + rowBoff) * 128 + boffs;
                uint32_t bh0, bh1, bh2, bh3, bl0, bl1, bl2, bl3;
                ldsm4(bbase, bh0, bh1, bh2, bh3);
                ldsm4(bbase + 16384, bl0, bl1, bl2, bl3);
                int f0 = np * 2, f1 = np * 2 + 1;
                mma_bf16(acc[f0][0], acc[f0][1], acc[f0][2], acc[f0][3],
                         Ah[ks][0], Ah[ks][1], Ah[ks][2], Ah[ks][3], bh0, bh1);
                mma_bf16(acc[f1][0], acc[f1][1], acc[f1][2], acc[f1][3],
                         Ah[ks][0], Ah[ks][1], Ah[ks][2], Ah[ks][3], bh2, bh3);
                mma_bf16(acc[f0][0], acc[f0][1], acc[f0][2], acc[f0][3],
                         Ah[ks][0], Ah[ks][1], Ah[ks][2], Ah[ks][3], bl0, bl1);
                mma_bf16(acc[f1][0], acc[f1][1], acc[f1][2], acc[f1][3],
                         Ah[ks][0], Ah[ks][1], Ah[ks][2], Ah[ks][3], bl2, bl3);
                mma_bf16(acc[f0][0], acc[f0][1], acc[f0][2], acc[f0][3],
                         Al[ks][0], Al[ks][1], Al[ks][2], Al[ks][3], bh0, bh1);
                mma_bf16(acc[f1][0], acc[f1][1], acc[f1][2], acc[f1][3],
                         Al[ks][0], Al[ks][1], Al[ks][2], Al[ks][3], bh2, bh3);
            }
        }

#pragma unroll
        for (int h2 = 0; h2 < 2; h2++) {
            float tmax = -1e30f;
#pragma unroll
            for (int nf = 0; nf < 16; nf++)
                tmax = fmaxf(tmax, fmaxf(acc[nf][h2 * 2], acc[nf][h2 * 2 + 1]));
            float nm = fmaxf(mst[h2], tmax);
            float f = ex2f(mst[h2] - nm);
            float zs = 0.f, ts = 0.f;
#pragma unroll
            for (int nf = 0; nf < 16; nf++) {
                float u0 = acc[nf][h2 * 2];
                float u1 = acc[nf][h2 * 2 + 1];
                float e0 = ex2f(u0 - nm);
                float e1 = ex2f(u1 - nm);
                zs += e0 + e1;
                ts = fmaf(e0, u0, ts);
                ts = fmaf(e1, u1, ts);
            }
            Zc[h2] = Zc[h2] * f + zs;
            Tc[h2] = Tc[h2] * f + ts;
            mst[h2] = nm;
        }
        __syncthreads();
    }

#pragma unroll
    for (int h2 = 0; h2 < 2; h2++) {
#pragma unroll
        for (int off = 1; off < 4; off <<= 1) {
            float mo = __shfl_xor_sync(0xffffffffu, mst[h2], off, 4);
            float zo = __shfl_xor_sync(0xffffffffu, Zc[h2],  off, 4);
            float to = __shfl_xor_sync(0xffffffffu, Tc[h2],  off, 4);
            float nm = fmaxf(mst[h2], mo);
            float f1 = ex2f(mst[h2] - nm), f2 = ex2f(mo - nm);
            Zc[h2] = Zc[h2] * f1 + zo * f2;
            Tc[h2] = Tc[h2] * f1 + to * f2;
            mst[h2] = nm;
        }
        if ((lane & 3) == 0) {
            int q = q0 + wrow0 + (lane >> 2) + h2 * 8;
            size_t o = ((size_t)zk * BH * TT + (size_t)bh * TT + q) * 4;
            *(float4*)&g_kp[o] = make_float4(mst[h2], Zc[h2], Tc[h2], 0.f);
        }
    }
}

// ---------------------------------------------------------------------------
// Top-3: segmented partials. grid (8 seg, 16 bh), 256 thr, 1 q per thread.
// Fuses the split-K KL merge. jax tie semantics (value desc, index asc).
// ---------------------------------------------------------------------------
__device__ __forceinline__ bool cand_better(float av, int ai, float bv, int bi) {
    return av > bv || (av == bv && ai < bi);
}

__global__ void top3_part_kernel() {
    const int seg = blockIdx.x;
    const int bh = blockIdx.y;
    const int tid = threadIdx.x;
    const int q = seg * 256 + tid;
    __shared__ float sv[256 * 3];
    __shared__ int   si[256 * 3];

    float4 p0 = *(float4*)&g_kp[((size_t)bh * TT + q) * 4];
    float4 p1 = *(float4*)&g_kp[((size_t)BH * TT + (size_t)bh * TT + q) * 4];
    float nm = fmaxf(p0.x, p1.x);
    float f0 = ex2f(p0.x - nm), f1 = ex2f(p1.x - nm);
    float Z = p0.y * f0 + p1.y * f1;
    float T = p0.z * f0 + p1.z * f1;
    float v = 0.6931471805599453f * (T / Z - nm - log2f(Z));

    sv[tid*3+0] = v;      si[tid*3+0] = q;
    sv[tid*3+1] = -1e38f; si[tid*3+1] = TT;
    sv[tid*3+2] = -1e38f; si[tid*3+2] = TT;
    __syncthreads();

    for (int s = 128; s > 0; s >>= 1) {
        if (tid < s) {
            float av[3], bvv[3]; int ai[3], bii[3];
#pragma unroll
            for (int j = 0; j < 3; j++) {
                av[j] = sv[tid*3+j];        ai[j] = si[tid*3+j];
                bvv[j] = sv[(tid+s)*3+j];   bii[j] = si[(tid+s)*3+j];
            }
            float ov[3]; int oi[3];
            int pa = 0, pb = 0;
#pragma unroll
            for (int j = 0; j < 3; j++) {
                if (cand_better(av[pa], ai[pa], bvv[pb], bii[pb])) {
                    ov[j] = av[pa]; oi[j] = ai[pa]; pa++;
                } else {
                    ov[j] = bvv[pb]; oi[j] = bii[pb]; pb++;
                }
            }
#pragma unroll
            for (int j = 0; j < 3; j++) { sv[tid*3+j] = ov[j]; si[tid*3+j] = oi[j]; }
        }
        __syncthreads();
    }

    if (tid < 3) {
        g_t3v[(bh * 8 + seg) * 3 + tid] = sv[tid];
        g_t3i[(bh * 8 + seg) * 3 + tid] = si[tid];
    }
}

// merge the 8 sorted segment triples for bh; return index of rank u
__device__ int pick_top(int bh, int u) {
    float bv[3] = {-1e38f, -1e38f, -1e38f};
    int   bi[3] = {TT, TT, TT};
    for (int seg = 0; seg < 8; seg++) {
        const float* pv = g_t3v + (bh * 8 + seg) * 3;
        const int*   pi = g_t3i + (bh * 8 + seg) * 3;
        float av[3] = {bv[0], bv[1], bv[2]};
        int   ai[3] = {bi[0], bi[1], bi[2]};
        float cv[3] = {pv[0], pv[1], pv[2]};
        int   ci[3] = {pi[0], pi[1], pi[2]};
        int pa = 0, pb = 0;
#pragma unroll
        for (int j = 0; j < 3; j++) {
            if (cand_better(av[pa], ai[pa], cv[pb], ci[pb])) {
                bv[j] = av[pa]; bi[j] = ai[pa]; pa++;
            } else {
                bv[j] = cv[pb]; bi[j] = ci[pb]; pb++;
            }
        }
    }
    return bi[u];
}

// ---------------------------------------------------------------------------
// Reduced attention, split-K: grid (48 slots, 8 parts), 256 keys per part.
// ---------------------------------------------------------------------------
__global__ __launch_bounds__(256) void redattn_part_kernel() {
    const int slot = blockIdx.x;
    const int part = blockIdx.y;
    const int bh = slot / UU;
    __shared__ int s_t;
    __shared__ float qrow[64];
    __shared__ float sarr[256];
    __shared__ float red[256];
    const int tid = threadIdx.x;

    if (tid == 0) s_t = pick_top(bh, slot % UU);
    __syncthreads();
    const int t = s_t;

    if (tid < 64) qrow[tid] = g_Q[((size_t)bh * TT + t) * DD + tid];
    __syncthreads();

    const int k = part * 256 + tid;
    {
        const float* kr = g_K + ((size_t)bh * TT + k) * DD;
        float s = 0.f;
#pragma unroll
        for (int d = 0; d < 64; d++) s = fmaf(qrow[d], kr[d], s);
        s *= 0.125f;
        if (!(s == s)) s = -10000.0f;
        s = fminf(fmaxf(s, -10000.0f), 10000.0f);
        sarr[tid] = s;
        red[tid] = s;
    }
    __syncthreads();
    for (int s = 128; s > 0; s >>= 1) {
        if (tid < s) red[tid] = fmaxf(red[tid], red[tid + s]);
        __syncthreads();
    }
    const float mx = red[0];
    __syncthreads();

    float e = expf(sarr[tid] - mx);
    sarr[tid] = e;
    red[tid] = e;
    __syncthreads();
    for (int s = 128; s > 0; s >>= 1) {
        if (tid < s) red[tid] += red[tid + s];
        __syncthreads();
    }
    const float Zp = red[0];
    __syncthreads();

    const int d = tid % 64, gi = tid / 64;
    float acc = 0.f;
    for (int kk = gi; kk < 256; kk += 4)
        acc = fmaf(sarr[kk], g_V[((size_t)bh * TT + part * 256 + kk) * DD + d], acc);
    red[tid] = acc; __syncthreads();

    float* pp = g_part + (size_t)(slot * 8 + part) * 68;
    if (tid == 0) { pp[0] = mx; pp[1] = Zp; }
    if (tid < 64)
        pp[2 + tid] = red[tid] + red[tid + 64] + red[tid + 128] + red[tid + 192];
}

// ---------------------------------------------------------------------------
// Output: init to bias (float4); scatter fuses combine + top pick + Wo proj
// ---------------------------------------------------------------------------
__global__ void init_out_kernel(float* __restrict__ out, const float* __restrict__ bo) {
    int idx = blockIdx.x * 256 + threadIdx.x;   // over (B*T*DM)/4
    int c4 = idx & 127;                          // 512/4 columns
    *(float4*)&out[(size_t)idx * 4] = *(const float4*)&bo[c4 * 4];
}

__global__ void scatter_kernel(const float* __restrict__ Wo, float* __restrict__ out) {
    const int slot = blockIdx.x;
    const int bh = slot / UU;
    const int b = bh / HH, h = bh % HH;
    __shared__ int s_t;
    __shared__ float orow[64];

    if (threadIdx.x == 0) s_t = pick_top(bh, slot % UU);
    __syncthreads();
    const int t = s_t;

    if (threadIdx.x < 64) {
        const int d = threadIdx.x;
        float mstar = -1e30f;
#pragma unroll
        for (int p = 0; p < 8; p++)
            mstar = fmaxf(mstar, g_part[(size_t)(slot * 8 + p) * 68]);
        float Z = 0.f, acc = 0.f;
#pragma unroll
        for (int p = 0; p < 8; p++) {
            const float* pp = g_part + (size_t)(slot * 8 + p) * 68;
            float f = expf(pp[0] - mstar);
            Z += pp[1] * f;
            acc += pp[2 + d] * f;
        }
        orow[d] = acc / Z;
    }
    __syncthreads();

    for (int n = threadIdx.x; n < DMM; n += 256) {
        const float* wr = Wo + (size_t)n * DMM + h * DD;
        float acc = 0.f;
#pragma unroll
        for (int d = 0; d < 64; d++) acc = fmaf(orow[d], wr[d], acc);
        atomicAdd(&out[((size_t)b * TT + t) * DMM + n], acc);
    }
}

// ---------------------------------------------------------------------------
extern "C" void kernel_launch(void* const* d_in, const int* in_sizes, int n_in,
                              void* d_out, int out_size) {
    const float* query = (const float*)d_in[0];
    const float* key   = (const float*)d_in[1];
    const float* value = (const float*)d_in[2];
    const float* Wq = (const float*)d_in[3];
    const float* bq = (const float*)d_in[4];
    const float* Wk = (const float*)d_in[5];
    const float* bk = (const float*)d_in[6];
    const float* Wv = (const float*)d_in[7];
    const float* bv = (const float*)d_in[8];
    const float* Wo = (const float*)d_in[9];
    const float* bo = (const float*)d_in[10];
    float* out = (float*)d_out;

    float *Qp, *Kp, *Vp;
    cudaGetSymbolAddress((void**)&Qp, g_Q);
    cudaGetSymbolAddress((void**)&Kp, g_K);
    cudaGetSymbolAddress((void**)&Vp, g_V);

    const int proj_smem = 65536 + 1024;
    const int kl_smem   = 65536 + 1024;
    cudaFuncSetAttribute(proj_mma_kernel, cudaFuncAttributeMaxDynamicSharedMemorySize, proj_smem);
    cudaFuncSetAttribute(kl_mma_kernel,   cudaFuncAttributeMaxDynamicSharedMemorySize, kl_smem);

    conv_kernel<<<dim3(1152, 3), 256>>>(query, key, value, Wq, Wk, Wv);

    proj_mma_kernel<<<dim3(4, 32, 3), 256, proj_smem>>>(bq, bk, bv, Qp, Kp, Vp);

    kl_mma_kernel<<<dim3(16, 16, 2), 256, kl_smem>>>();

    top3_part_kernel<<<dim3(8, BH), 256>>>();
    redattn_part_kernel<<<dim3(BH * UU, 8), 256>>>();

    init_out_kernel<<<(BB * TT * DMM / 4 + 255) / 256, 256>>>(out, bo);
    scatter_kernel<<<BH * UU, 256>>>(Wo, out);
}

// round 16
// speedup vs baseline: 1.1895x; 1.0934x over previous
#include <cuda_runtime.h>
#include <cuda_bf16.h>
#include <math.h>
#include <stdint.h>

#define BB 2
#define TT 2048
#define DMM 512
#define HH 8
#define DD 64
#define UU 3
#define BH (BB*HH)

typedef unsigned long long u64;

// fp32 scratch
__device__ float g_Q[BH*TT*DD];    // [b,h,t,d]
__device__ float g_K[BH*TT*DD];
__device__ float g_V[BH*TT*DD];
__device__ float g_part[BH*UU*8*68];
__device__ float g_kp[2*BH*TT*4];   // kl split-K partials: m, Z, T, pad
__device__ float g_t3v[BH*2*3];     // per-(bh,seg) top-3 values (sorted)
__device__ int   g_t3i[BH*2*3];

// bf16 hi/lo packed (bf16x2 per uint), row-major
__device__ unsigned g_Xh[3*4096*256];   // [z][m][k/2]
__device__ unsigned g_Xl[3*4096*256];
__device__ unsigned g_Wh[3*512*256];    // [z][n][k/2]
__device__ unsigned g_Wl[3*512*256];
__device__ unsigned g_Qh[BH*TT*32];     // [bh][t][d/2]  (scaled by log2e/8)
__device__ unsigned g_Ql[BH*TT*32];
__device__ unsigned g_Kh[BH*TT*32];
__device__ unsigned g_Kl[BH*TT*32];     // produced (cheap) but unused by kl

// ---------------------------------------------------------------------------
__device__ __forceinline__ uint32_t smem_u32(const void* p) {
    uint32_t a;
    asm("{ .reg .u64 t; cvta.to.shared.u64 t, %1; cvt.u32.u64 %0, t; }" : "=r"(a) : "l"(p));
    return a;
}
__device__ __forceinline__ void ldsm4(uint32_t addr, uint32_t& r0, uint32_t& r1,
                                      uint32_t& r2, uint32_t& r3) {
    asm volatile("ldmatrix.sync.aligned.m8n8.x4.shared.b16 {%0,%1,%2,%3}, [%4];"
                 : "=r"(r0), "=r"(r1), "=r"(r2), "=r"(r3) : "r"(addr));
}
__device__ __forceinline__ void mma_bf16(float& c0, float& c1, float& c2, float& c3,
                                         uint32_t a0, uint32_t a1, uint32_t a2, uint32_t a3,
                                         uint32_t b0, uint32_t b1) {
    asm("mma.sync.aligned.m16n8k16.row.col.f32.bf16.bf16.f32 "
        "{%0,%1,%2,%3}, {%4,%5,%6,%7}, {%8,%9}, {%0,%1,%2,%3};"
        : "+f"(c0), "+f"(c1), "+f"(c2), "+f"(c3)
        : "r"(a0), "r"(a1), "r"(a2), "r"(a3), "r"(b0), "r"(b1));
}
__device__ __forceinline__ float ex2f(float x) {
    float r;
    asm("ex2.approx.ftz.f32 %0, %1;" : "=f"(r) : "f"(x));
    return r;
}
#define CP_ASYNC16(dst, src) \
    asm volatile("cp.async.cg.shared.global [%0], [%1], 16;" :: "r"(dst), "l"(src))
#define CP_COMMIT() asm volatile("cp.async.commit_group;" ::: "memory")
#define CP_WAIT1()  asm volatile("cp.async.wait_group 1;" ::: "memory")
#define CP_WAIT0()  asm volatile("cp.async.wait_group 0;" ::: "memory")

// ---------------------------------------------------------------------------
// fp32 -> bf16 hi/lo split + fused conversion (X and W in one launch)
// ---------------------------------------------------------------------------
__device__ __forceinline__ void split8(const float* src, uint4& hi, uint4& lo) {
    float4 a = *(const float4*)src;
    float4 b = *(const float4*)(src + 4);
    float v[8] = {a.x, a.y, a.z, a.w, b.x, b.y, b.z, b.w};
    unsigned h16[8], l16[8];
#pragma unroll
    for (int i = 0; i < 8; i++) {
        __nv_bfloat16 h = __float2bfloat16_rn(v[i]);
        float r = v[i] - __bfloat162float(h);
        __nv_bfloat16 l = __float2bfloat16_rn(r);
        h16[i] = __bfloat16_as_ushort(h);
        l16[i] = __bfloat16_as_ushort(l);
    }
    hi = make_uint4(h16[0] | (h16[1] << 16), h16[2] | (h16[3] << 16),
                    h16[4] | (h16[5] << 16), h16[6] | (h16[7] << 16));
    lo = make_uint4(l16[0] | (l16[1] << 16), l16[2] | (l16[3] << 16),
                    l16[4] | (l16[5] << 16), l16[6] | (l16[7] << 16));
}

__global__ __launch_bounds__(256) void conv_kernel(
    const float* __restrict__ X0, const float* __restrict__ X1, const float* __restrict__ X2,
    const float* __restrict__ W0, const float* __restrict__ W1, const float* __restrict__ W2)
{
    const int z = blockIdx.y;
    if (blockIdx.x < 1024) {
        const float* X = (z == 0) ? X0 : (z == 1) ? X1 : X2;
        int idx = blockIdx.x * 256 + threadIdx.x;
        uint4 hi, lo;
        split8(X + (size_t)idx * 8, hi, lo);
        size_t di = (size_t)z * 4096 * 64 + idx;
        ((uint4*)g_Xh)[di] = hi;
        ((uint4*)g_Xl)[di] = lo;
    } else {
        const float* W = (z == 0) ? W0 : (z == 1) ? W1 : W2;
        int idx = (blockIdx.x - 1024) * 256 + threadIdx.x;
        uint4 hi, lo;
        split8(W + (size_t)idx * 8, hi, lo);
        size_t di = (size_t)z * 512 * 64 + idx;
        ((uint4*)g_Wh)[di] = hi;
        ((uint4*)g_Wl)[di] = lo;
    }
}

// ---------------------------------------------------------------------------
// Projection via mma.sync bf16 3-term split, cp.async double-buffered, k32
// stages with SW64 swizzle. grid (nt=4, mt=32, z=3), 256 thr. Tile 128x128.
// ---------------------------------------------------------------------------
__global__ __launch_bounds__(256, 2) void proj_mma_kernel(
    const float* __restrict__ B0, const float* __restrict__ B1, const float* __restrict__ B2,
    float* __restrict__ P0, float* __restrict__ P1, float* __restrict__ P2)
{
    extern __shared__ char dsm[];
    char* sbase = (char*)(((uintptr_t)dsm + 1023u) & ~(uintptr_t)1023u);
    const uint32_t sb = smem_u32(sbase);

    const int z = blockIdx.z;
    const float* Bv = (z == 0) ? B0 : (z == 1) ? B1 : B2;
    float*       P = (z == 0) ? P0 : (z == 1) ? P1 : P2;
    const int nt = blockIdx.x, mt = blockIdx.y;
    const int tid = threadIdx.x;
    const int wid = tid >> 5, lane = tid & 31;
    const int r = lane & 7, g = lane >> 3;
    const int wrow0 = wid * 16;
    const int m0 = mt * 128, n0 = nt * 128;

    float acc[16][4];
#pragma unroll
    for (int i = 0; i < 16; i++)
#pragma unroll
        for (int j = 0; j < 4; j++) acc[i][j] = 0.f;

    const int rowA = wrow0 + r + (g & 1) * 8;
    const int gbA = g >> 1;
    const int gbB = g & 1;
    const int rowBoff = r + ((g >> 1) & 1) * 8;

    const uint32_t rbA = (uint32_t)rowA * 64;
    const uint32_t maskA = (rbA >> 3) & 0x30;

    auto prefetch = [&](int kc) {
        uint32_t stg = sb + (kc & 1) * 32768;
#pragma unroll
        for (int j = 0; j < 2; j++) {
            int i = tid + j * 256;
            int row = i >> 2, c = i & 3;
            uint32_t boff = row * 64 + c * 16;
            uint32_t swb = boff ^ ((boff >> 3) & 0x30);
            size_t sx = (size_t)(z * 4096 + m0 + row) * 64 + kc * 4 + c;
            size_t swi = (size_t)(z * 512 + n0 + row) * 64 + kc * 4 + c;
            CP_ASYNC16(stg + swb,         (const uint4*)g_Xh + sx);
            CP_ASYNC16(stg + 8192 + swb,  (const uint4*)g_Xl + sx);
            CP_ASYNC16(stg + 16384 + swb, (const uint4*)g_Wh + swi);
            CP_ASYNC16(stg + 24576 + swb, (const uint4*)g_Wl + swi);
        }
    };

    prefetch(0); CP_COMMIT();

    for (int kc = 0; kc < 16; kc++) {
        if (kc < 15) { prefetch(kc + 1); CP_COMMIT(); CP_WAIT1(); }
        else CP_WAIT0();
        __syncthreads();
        const uint32_t stg = sb + (kc & 1) * 32768;
        const uint32_t abase = stg + rbA;

#pragma unroll
        for (int ks = 0; ks < 2; ks++) {
            uint32_t aoffs = ((uint32_t)((ks * 2 + gbA) * 16)) ^ maskA;
            uint32_t ah0, ah1, ah2, ah3, al0, al1, al2, al3;
            ldsm4(abase + aoffs, ah0, ah1, ah2, ah3);
            ldsm4(abase + 8192 + aoffs, al0, al1, al2, al3);
            uint32_t chunkB = (uint32_t)((ks * 2 + gbB) * 16);
#pragma unroll
            for (int np = 0; np < 8; np++) {
                uint32_t rbB = (uint32_t)(np * 16 + rowBoff) * 64;
                uint32_t boffs = chunkB ^ ((rbB >> 3) & 0x30);
                uint32_t bbase = stg + 16384 + rbB + boffs;
                uint32_t bh0, bh1, bh2, bh3, bl0, bl1, bl2, bl3;
                ldsm4(bbase, bh0, bh1, bh2, bh3);
                ldsm4(bbase + 8192, bl0, bl1, bl2, bl3);
                int f0 = np * 2, f1 = np * 2 + 1;
                mma_bf16(acc[f0][0], acc[f0][1], acc[f0][2], acc[f0][3],
                         ah0, ah1, ah2, ah3, bh0, bh1);
                mma_bf16(acc[f1][0], acc[f1][1], acc[f1][2], acc[f1][3],
                         ah0, ah1, ah2, ah3, bh2, bh3);
                mma_bf16(acc[f0][0], acc[f0][1], acc[f0][2], acc[f0][3],
                         ah0, ah1, ah2, ah3, bl0, bl1);
                mma_bf16(acc[f1][0], acc[f1][1], acc[f1][2], acc[f1][3],
                         ah0, ah1, ah2, ah3, bl2, bl3);
                mma_bf16(acc[f0][0], acc[f0][1], acc[f0][2], acc[f0][3],
                         al0, al1, al2, al3, bh0, bh1);
                mma_bf16(acc[f1][0], acc[f1][1], acc[f1][2], acc[f1][3],
                         al0, al1, al2, al3, bh2, bh3);
            }
        }
        __syncthreads();
    }

    const float QSCALE = 0.18033688011112042f;   // 0.125 * log2(e)
    const int mrow0 = m0 + wrow0 + (lane >> 2);
#pragma unroll
    for (int half = 0; half < 2; half++) {
        int m = mrow0 + half * 8;
        int b = m >> 11, t = m & 2047;
#pragma unroll
        for (int nf = 0; nf < 16; nf++) {
            int n = n0 + nf * 8 + 2 * (lane & 3);
            int h = n >> 6, d = n & 63;
            float2 bias = *(const float2*)(Bv + n);
            float v0 = acc[nf][half * 2] + bias.x;
            float v1 = acc[nf][half * 2 + 1] + bias.y;
            size_t po = (((size_t)(b * HH + h)) * TT + t) * DD + d;
            *(float2*)&P[po] = make_float2(v0, v1);
            if (z < 2) {
                float s0 = v0, s1 = v1;
                if (z == 0) { s0 *= QSCALE; s1 *= QSCALE; }
                __nv_bfloat16 h0 = __float2bfloat16_rn(s0);
                __nv_bfloat16 h1 = __float2bfloat16_rn(s1);
                float l0 = s0 - __bfloat162float(h0);
                float l1 = s1 - __bfloat162float(h1);
                unsigned hp = (unsigned)__bfloat16_as_ushort(h0) |
                              ((unsigned)__bfloat16_as_ushort(h1) << 16);
                unsigned lp = (unsigned)__bfloat16_as_ushort(__float2bfloat16_rn(l0)) |
                              ((unsigned)__bfloat16_as_ushort(__float2bfloat16_rn(l1)) << 16);
                size_t qo = (((size_t)(b * HH + h)) * TT + t) * 32 + (d >> 1);
                if (z == 0) { g_Qh[qo] = hp; g_Ql[qo] = lp; }
                else        { g_Kh[qo] = hp; g_Kl[qo] = lp; }
            }
        }
    }
}

// ---------------------------------------------------------------------------
// KL statistic: 2-term split (Ah·Bh + Al·Bh — K bf16-rounded; selection-only
// path, output values unaffected). Base-2 online softmax, split-K (zk=2).
// grid (qt=16, bh=16, zk=2), 256 thr. smem: 2 Kh stages x 16KB = 32KB.
// ---------------------------------------------------------------------------
__global__ __launch_bounds__(256, 2) void kl_mma_kernel() {
    extern __shared__ char dsm[];
    char* sbase = (char*)(((uintptr_t)dsm + 1023u) & ~(uintptr_t)1023u);
    const uint32_t sb = smem_u32(sbase);

    const int tid = threadIdx.x;
    const int wid = tid >> 5, lane = tid & 31;
    const int r = lane & 7, g = lane >> 3;
    const int wrow0 = wid * 16;
    const int bh = blockIdx.y;
    const int q0 = blockIdx.x * 128;
    const int zk = blockIdx.z;

    auto prefetchK = [&](int ktl) {
        uint32_t stg = sb + (ktl & 1) * 16384;
        int ktg = zk * 8 + ktl;
#pragma unroll
        for (int j = 0; j < 4; j++) {
            int i = tid + j * 256;
            int row = i >> 3, c = i & 7;
            uint32_t boff = row * 128 + c * 16;
            uint32_t swb = boff ^ ((boff >> 3) & 0x70);
            size_t sidx = (size_t)(bh * TT + ktg * 128 + row) * 8 + c;
            CP_ASYNC16(stg + swb, (const uint4*)g_Kh + sidx);
        }
    };

    prefetchK(0); CP_COMMIT();

    uint32_t Ah[4][4], Al[4][4];
    {
        const int row0 = q0 + wrow0 + (lane >> 2);
        const size_t qb0 = ((size_t)bh * TT + row0) * 32;
        const size_t qb1 = qb0 + 8 * 32;
#pragma unroll
        for (int ks = 0; ks < 4; ks++) {
            int cu = ks * 8 + (lane & 3);
            Ah[ks][0] = g_Qh[qb0 + cu];
            Ah[ks][1] = g_Qh[qb1 + cu];
            Ah[ks][2] = g_Qh[qb0 + cu + 4];
            Ah[ks][3] = g_Qh[qb1 + cu + 4];
            Al[ks][0] = g_Ql[qb0 + cu];
            Al[ks][1] = g_Ql[qb1 + cu];
            Al[ks][2] = g_Ql[qb0 + cu + 4];
            Al[ks][3] = g_Ql[qb1 + cu + 4];
        }
    }

    float mst[2] = {-1e30f, -1e30f}, Zc[2] = {0.f, 0.f}, Tc[2] = {0.f, 0.f};
    const int gbB = g & 1;
    const int rowBoff = r + ((g >> 1) & 1) * 8;

    for (int ktl = 0; ktl < 8; ktl++) {
        if (ktl < 7) { prefetchK(ktl + 1); CP_COMMIT(); CP_WAIT1(); }
        else CP_WAIT0();
        __syncthreads();
        const uint32_t stg = sb + (ktl & 1) * 16384;

        float acc[16][4];
#pragma unroll
        for (int i = 0; i < 16; i++)
#pragma unroll
            for (int j = 0; j < 4; j++) acc[i][j] = 0.f;

#pragma unroll
        for (int ks = 0; ks < 4; ks++) {
            uint32_t boffs = ((uint32_t)((ks * 2 + gbB) * 16)) ^ (uint32_t)(r * 16);
#pragma unroll
            for (int np = 0; np < 8; np++) {
                uint32_t bbase = stg + (np * 16 + rowBoff) * 128 + boffs;
                uint32_t bh0, bh1, bh2, bh3;
                ldsm4(bbase, bh0, bh1, bh2, bh3);
                int f0 = np * 2, f1 = np * 2 + 1;
                mma_bf16(acc[f0][0], acc[f0][1], acc[f0][2], acc[f0][3],
                         Ah[ks][0], Ah[ks][1], Ah[ks][2], Ah[ks][3], bh0, bh1);
                mma_bf16(acc[f1][0], acc[f1][1], acc[f1][2], acc[f1][3],
                         Ah[ks][0], Ah[ks][1], Ah[ks][2], Ah[ks][3], bh2, bh3);
                mma_bf16(acc[f0][0], acc[f0][1], acc[f0][2], acc[f0][3],
                         Al[ks][0], Al[ks][1], Al[ks][2], Al[ks][3], bh0, bh1);
                mma_bf16(acc[f1][0], acc[f1][1], acc[f1][2], acc[f1][3],
                         Al[ks][0], Al[ks][1], Al[ks][2], Al[ks][3], bh2, bh3);
            }
        }

#pragma unroll
        for (int h2 = 0; h2 < 2; h2++) {
            float tmax = -1e30f;
#pragma unroll
            for (int nf = 0; nf < 16; nf++)
                tmax = fmaxf(tmax, fmaxf(acc[nf][h2 * 2], acc[nf][h2 * 2 + 1]));
            float nm = fmaxf(mst[h2], tmax);
            float f = ex2f(mst[h2] - nm);
            float zs = 0.f, ts = 0.f;
#pragma unroll
            for (int nf = 0; nf < 16; nf++) {
                float u0 = acc[nf][h2 * 2];
                float u1 = acc[nf][h2 * 2 + 1];
                float e0 = ex2f(u0 - nm);
                float e1 = ex2f(u1 - nm);
                zs += e0 + e1;
                ts = fmaf(e0, u0, ts);
                ts = fmaf(e1, u1, ts);
            }
            Zc[h2] = Zc[h2] * f + zs;
            Tc[h2] = Tc[h2] * f + ts;
            mst[h2] = nm;
        }
        __syncthreads();
    }

#pragma unroll
    for (int h2 = 0; h2 < 2; h2++) {
#pragma unroll
        for (int off = 1; off < 4; off <<= 1) {
            float mo = __shfl_xor_sync(0xffffffffu, mst[h2], off, 4);
            float zo = __shfl_xor_sync(0xffffffffu, Zc[h2],  off, 4);
            float to = __shfl_xor_sync(0xffffffffu, Tc[h2],  off, 4);
            float nm = fmaxf(mst[h2], mo);
            float f1 = ex2f(mst[h2] - nm), f2 = ex2f(mo - nm);
            Zc[h2] = Zc[h2] * f1 + zo * f2;
            Tc[h2] = Tc[h2] * f1 + to * f2;
            mst[h2] = nm;
        }
        if ((lane & 3) == 0) {
            int q = q0 + wrow0 + (lane >> 2) + h2 * 8;
            size_t o = ((size_t)zk * BH * TT + (size_t)bh * TT + q) * 4;
            *(float4*)&g_kp[o] = make_float4(mst[h2], Zc[h2], Tc[h2], 0.f);
        }
    }
}

// ---------------------------------------------------------------------------
// Top-3: segmented partials. grid (2 seg, 16 bh), 256 thr, 4 q per thread.
// Fuses the split-K KL merge. jax tie semantics (value desc, index asc).
// ---------------------------------------------------------------------------
__device__ __forceinline__ bool cand_better(float av, int ai, float bv, int bi) {
    return av > bv || (av == bv && ai < bi);
}

__global__ void top3_part_kernel() {
    const int seg = blockIdx.x;
    const int bh = blockIdx.y;
    const int tid = threadIdx.x;
    __shared__ float sv[256 * 3];
    __shared__ int   si[256 * 3];

    float tv[3] = {-1e38f, -1e38f, -1e38f};
    int   ti[3] = {TT, TT, TT};

#pragma unroll
    for (int j = 0; j < 4; j++) {
        int q = seg * 1024 + j * 256 + tid;
        float4 p0 = *(float4*)&g_kp[((size_t)bh * TT + q) * 4];
        float4 p1 = *(float4*)&g_kp[((size_t)BH * TT + (size_t)bh * TT + q) * 4];
        float nm = fmaxf(p0.x, p1.x);
        float f0 = ex2f(p0.x - nm), f1 = ex2f(p1.x - nm);
        float Z = p0.y * f0 + p1.y * f1;
        float T = p0.z * f0 + p1.z * f1;
        float v = 0.6931471805599453f * (T / Z - nm - log2f(Z));
        if (cand_better(v, q, tv[0], ti[0])) {
            tv[2] = tv[1]; ti[2] = ti[1];
            tv[1] = tv[0]; ti[1] = ti[0];
            tv[0] = v; ti[0] = q;
        } else if (cand_better(v, q, tv[1], ti[1])) {
            tv[2] = tv[1]; ti[2] = ti[1];
            tv[1] = v; ti[1] = q;
        } else if (cand_better(v, q, tv[2], ti[2])) {
            tv[2] = v; ti[2] = q;
        }
    }

    sv[tid*3+0] = tv[0]; si[tid*3+0] = ti[0];
    sv[tid*3+1] = tv[1]; si[tid*3+1] = ti[1];
    sv[tid*3+2] = tv[2]; si[tid*3+2] = ti[2];
    __syncthreads();

    for (int s = 128; s > 0; s >>= 1) {
        if (tid < s) {
            float av[3], bvv[3]; int ai[3], bii[3];
#pragma unroll
            for (int j = 0; j < 3; j++) {
                av[j] = sv[tid*3+j];        ai[j] = si[tid*3+j];
                bvv[j] = sv[(tid+s)*3+j];   bii[j] = si[(tid+s)*3+j];
            }
            float ov[3]; int oi[3];
            int pa = 0, pb = 0;
#pragma unroll
            for (int j = 0; j < 3; j++) {
                if (cand_better(av[pa], ai[pa], bvv[pb], bii[pb])) {
                    ov[j] = av[pa]; oi[j] = ai[pa]; pa++;
                } else {
                    ov[j] = bvv[pb]; oi[j] = bii[pb]; pb++;
                }
            }
#pragma unroll
            for (int j = 0; j < 3; j++) { sv[tid*3+j] = ov[j]; si[tid*3+j] = oi[j]; }
        }
        __syncthreads();
    }

    if (tid < 3) {
        g_t3v[(bh * 2 + seg) * 3 + tid] = sv[tid];
        g_t3i[(bh * 2 + seg) * 3 + tid] = si[tid];
    }
}

// merge the 2 sorted segment triples for bh; return index of rank u
__device__ int pick_top(int bh, int u) {
    const float* pv0 = g_t3v + (bh * 2 + 0) * 3;
    const int*   pi0 = g_t3i + (bh * 2 + 0) * 3;
    const float* pv1 = g_t3v + (bh * 2 + 1) * 3;
    const int*   pi1 = g_t3i + (bh * 2 + 1) * 3;
    float bv[3]; int bi[3];
    int pa = 0, pb = 0;
#pragma unroll
    for (int j = 0; j < 3; j++) {
        if (cand_better(pv0[pa], pi0[pa], pv1[pb], pi1[pb])) {
            bv[j] = pv0[pa]; bi[j] = pi0[pa]; pa++;
        } else {
            bv[j] = pv1[pb]; bi[j] = pi1[pb]; pb++;
        }
    }
    return bi[u];
}

// ---------------------------------------------------------------------------
// Reduced attention, split-K: grid (48 slots, 8 parts), 256 keys per part.
// ---------------------------------------------------------------------------
__global__ __launch_bounds__(256) void redattn_part_kernel() {
    const int slot = blockIdx.x;
    const int part = blockIdx.y;
    const int bh = slot / UU;
    __shared__ int s_t;
    __shared__ float qrow[64];
    __shared__ float sarr[256];
    __shared__ float red[256];
    const int tid = threadIdx.x;

    if (tid == 0) s_t = pick_top(bh, slot % UU);
    __syncthreads();
    const int t = s_t;

    if (tid < 64) qrow[tid] = g_Q[((size_t)bh * TT + t) * DD + tid];
    __syncthreads();

    const int k = part * 256 + tid;
    {
        const float* kr = g_K + ((size_t)bh * TT + k) * DD;
        float s = 0.f;
#pragma unroll
        for (int d = 0; d < 64; d++) s = fmaf(qrow[d], kr[d], s);
        s *= 0.125f;
        if (!(s == s)) s = -10000.0f;
        s = fminf(fmaxf(s, -10000.0f), 10000.0f);
        sarr[tid] = s;
        red[tid] = s;
    }
    __syncthreads();
    for (int s = 128; s > 0; s >>= 1) {
        if (tid < s) red[tid] = fmaxf(red[tid], red[tid + s]);
        __syncthreads();
    }
    const float mx = red[0];
    __syncthreads();

    float e = expf(sarr[tid] - mx);
    sarr[tid] = e;
    red[tid] = e;
    __syncthreads();
    for (int s = 128; s > 0; s >>= 1) {
        if (tid < s) red[tid] += red[tid + s];
        __syncthreads();
    }
    const float Zp = red[0];
    __syncthreads();

    const int d = tid % 64, gi = tid / 64;
    float acc = 0.f;
    for (int kk = gi; kk < 256; kk += 4)
        acc = fmaf(sarr[kk], g_V[((size_t)bh * TT + part * 256 + kk) * DD + d], acc);
    red[tid] = acc; __syncthreads();

    float* pp = g_part + (size_t)(slot * 8 + part) * 68;
    if (tid == 0) { pp[0] = mx; pp[1] = Zp; }
    if (tid < 64)
        pp[2 + tid] = red[tid] + red[tid + 64] + red[tid + 128] + red[tid + 192];
}

// ---------------------------------------------------------------------------
// Output: init to bias (float4); scatter fuses combine + top pick + Wo proj
// ---------------------------------------------------------------------------
__global__ void init_out_kernel(float* __restrict__ out, const float* __restrict__ bo) {
    int idx = blockIdx.x * 256 + threadIdx.x;   // over (B*T*DM)/4
    int c4 = idx & 127;
    *(float4*)&out[(size_t)idx * 4] = *(const float4*)&bo[c4 * 4];
}

__global__ void scatter_kernel(const float* __restrict__ Wo, float* __restrict__ out) {
    const int slot = blockIdx.x;
    const int bh = slot / UU;
    const int b = bh / HH, h = bh % HH;
    __shared__ int s_t;
    __shared__ float orow[64];

    if (threadIdx.x == 0) s_t = pick_top(bh, slot % UU);
    __syncthreads();
    const int t = s_t;

    if (threadIdx.x < 64) {
        const int d = threadIdx.x;
        float mstar = -1e30f;
#pragma unroll
        for (int p = 0; p < 8; p++)
            mstar = fmaxf(mstar, g_part[(size_t)(slot * 8 + p) * 68]);
        float Z = 0.f, acc = 0.f;
#pragma unroll
        for (int p = 0; p < 8; p++) {
            const float* pp = g_part + (size_t)(slot * 8 + p) * 68;
            float f = expf(pp[0] - mstar);
            Z += pp[1] * f;
            acc += pp[2 + d] * f;
        }
        orow[d] = acc / Z;
    }
    __syncthreads();

    for (int n = threadIdx.x; n < DMM; n += 256) {
        const float* wr = Wo + (size_t)n * DMM + h * DD;
        float acc = 0.f;
#pragma unroll
        for (int d = 0; d < 64; d++) acc = fmaf(orow[d], wr[d], acc);
        atomicAdd(&out[((size_t)b * TT + t) * DMM + n], acc);
    }
}

// ---------------------------------------------------------------------------
extern "C" void kernel_launch(void* const* d_in, const int* in_sizes, int n_in,
                              void* d_out, int out_size) {
    const float* query = (const float*)d_in[0];
    const float* key   = (const float*)d_in[1];
    const float* value = (const float*)d_in[2];
    const float* Wq = (const float*)d_in[3];
    const float* bq = (const float*)d_in[4];
    const float* Wk = (const float*)d_in[5];
    const float* bk = (const float*)d_in[6];
    const float* Wv = (const float*)d_in[7];
    const float* bv = (const float*)d_in[8];
    const float* Wo = (const float*)d_in[9];
    const float* bo = (const float*)d_in[10];
    float* out = (float*)d_out;

    float *Qp, *Kp, *Vp;
    cudaGetSymbolAddress((void**)&Qp, g_Q);
    cudaGetSymbolAddress((void**)&Kp, g_K);
    cudaGetSymbolAddress((void**)&Vp, g_V);

    const int proj_smem = 65536 + 1024;
    const int kl_smem   = 32768 + 1024;
    cudaFuncSetAttribute(proj_mma_kernel, cudaFuncAttributeMaxDynamicSharedMemorySize, proj_smem);
    cudaFuncSetAttribute(kl_mma_kernel,   cudaFuncAttributeMaxDynamicSharedMemorySize, kl_smem);

    conv_kernel<<<dim3(1152, 3), 256>>>(query, key, value, Wq, Wk, Wv);

    proj_mma_kernel<<<dim3(4, 32, 3), 256, proj_smem>>>(bq, bk, bv, Qp, Kp, Vp);

    kl_mma_kernel<<<dim3(16, 16, 2), 256, kl_smem>>>();

    top3_part_kernel<<<dim3(2, BH), 256>>>();
    redattn_part_kernel<<<dim3(BH * UU, 8), 256>>>();

    init_out_kernel<<<(BB * TT * DMM / 4 + 255) / 256, 256>>>(out, bo);
    scatter_kernel<<<BH * UU, 256>>>(Wo, out);
}